// round 2
// baseline (speedup 1.0000x reference)
#include <cuda_runtime.h>
#include <cstdint>

// Problem constants (fixed by the dataset)
#define N_TOK 8192
#define TOPK  2
#define NEXP  8
#define HDIM  2048
#define IDIM  1408
#define NSLOT (N_TOK * TOPK)          // 16384 routed slots

// GEMM tiling
#define BM   128
#define BK   8
#define BN1  64                        // per-half (gate / up) column tile in GEMM1
#define BN2  128                       // column tile in GEMM2
#define MAXT (NSLOT / BM + NEXP)       // 136 worst-case M-tiles

// -------------------- scratch (static device globals; no allocs) ------------
__device__ float g_inter[(size_t)NSLOT * IDIM];   // [16384, 1408] SwiGLU output
__device__ float g_outs [(size_t)NSLOT * HDIM];   // [16384, 2048] expert output
__device__ int   g_pos2slot[NSLOT];
__device__ int   g_slot2pos[NSLOT];
__device__ int   g_tile_e[MAXT];
__device__ int   g_tile_r0[MAXT];
__device__ int   g_tile_rows[MAXT];
__device__ int   g_ntiles;

// -------------------- routing: counts, offsets, tile schedule ---------------
__global__ void route_kernel(const int* __restrict__ topk_idx) {
    __shared__ int cnt[NEXP];
    __shared__ int cur[NEXP];
    int tid = threadIdx.x;
    if (tid < NEXP) cnt[tid] = 0;
    __syncthreads();
    for (int s = tid; s < NSLOT; s += blockDim.x)
        atomicAdd(&cnt[topk_idx[s]], 1);
    __syncthreads();
    if (tid == 0) {
        int off = 0, t = 0;
        for (int e = 0; e < NEXP; e++) {
            cur[e] = off;
            int c = cnt[e];
            for (int r = 0; r < c; r += BM) {
                g_tile_e[t]    = e;
                g_tile_r0[t]   = off + r;
                g_tile_rows[t] = (c - r < BM) ? (c - r) : BM;
                t++;
            }
            off += c;
        }
        g_ntiles = t;
    }
    __syncthreads();
    for (int s = tid; s < NSLOT; s += blockDim.x) {
        int p = atomicAdd(&cur[topk_idx[s]], 1);
        g_pos2slot[p] = s;
        g_slot2pos[s] = p;
    }
}

// -------------------- GEMM1: x[gather] @ gate_up + fused SwiGLU -------------
// Block computes a [128 x 64] gate tile AND the matching [128 x 64] up tile
// (columns c0..c0+63 and I+c0..I+c0+63), then writes silu(g)*u to g_inter.
__global__ __launch_bounds__(256) void gemm1_kernel(
    const float* __restrict__ x, const float* __restrict__ w /*[E,H,2I]*/) {
    int t = blockIdx.x;
    if (t >= g_ntiles) return;
    int e    = g_tile_e[t];
    int row0 = g_tile_r0[t];
    int rows = g_tile_rows[t];
    int c0   = blockIdx.y * BN1;

    __shared__ float As[BK][BM];
    __shared__ float Bg[BK][BN1];
    __shared__ float Bu[BK][BN1];
    __shared__ int   tok[BM];

    int tid = threadIdx.x;
    for (int i = tid; i < BM; i += 256) {
        int r = (i < rows) ? i : 0;               // clamp OOB rows to a valid one
        tok[i] = g_pos2slot[row0 + r] / TOPK;
    }
    __syncthreads();

    int aRow = tid >> 1;                          // 0..127
    int aK   = (tid & 1) * 4;                     // 0 or 4
    int bK   = tid >> 5;                          // 0..7
    int bCol = (tid & 31) * 2;                    // 0..62
    int ty   = tid >> 4;                          // 0..15 (8 rows each)
    int tx   = tid & 15;                          // 0..15 (4 cols each per half)

    const float* ap    = x + (size_t)tok[aRow] * HDIM + aK;
    const float* wbase = w + (size_t)e * HDIM * (2 * IDIM) + c0 + bCol;

    float accg[8][4], accu[8][4];
#pragma unroll
    for (int i = 0; i < 8; i++)
#pragma unroll
        for (int j = 0; j < 4; j++) { accg[i][j] = 0.f; accu[i][j] = 0.f; }

    for (int k0 = 0; k0 < HDIM; k0 += BK) {
        float4 av = *(const float4*)(ap + k0);
        As[aK + 0][aRow] = av.x;
        As[aK + 1][aRow] = av.y;
        As[aK + 2][aRow] = av.z;
        As[aK + 3][aRow] = av.w;
        const float* wr = wbase + (size_t)(k0 + bK) * (2 * IDIM);
        float2 g2 = *(const float2*)wr;
        float2 u2 = *(const float2*)(wr + IDIM);
        Bg[bK][bCol] = g2.x; Bg[bK][bCol + 1] = g2.y;
        Bu[bK][bCol] = u2.x; Bu[bK][bCol + 1] = u2.y;
        __syncthreads();
#pragma unroll
        for (int kk = 0; kk < BK; kk++) {
            float a[8], bg[4], bu[4];
#pragma unroll
            for (int i = 0; i < 8; i++) a[i] = As[kk][ty * 8 + i];
#pragma unroll
            for (int j = 0; j < 4; j++) { bg[j] = Bg[kk][tx * 4 + j]; bu[j] = Bu[kk][tx * 4 + j]; }
#pragma unroll
            for (int i = 0; i < 8; i++)
#pragma unroll
                for (int j = 0; j < 4; j++) {
                    accg[i][j] += a[i] * bg[j];
                    accu[i][j] += a[i] * bu[j];
                }
        }
        __syncthreads();
    }

#pragma unroll
    for (int i = 0; i < 8; i++) {
        int r = ty * 8 + i;
        if (r < rows) {
            float* op = g_inter + (size_t)(row0 + r) * IDIM + c0 + tx * 4;
#pragma unroll
            for (int j = 0; j < 4; j++) {
                float g = accg[i][j];
                float u = accu[i][j];
                op[j] = u * (g / (1.f + __expf(-g)));   // SwiGLU
            }
        }
    }
}

// -------------------- GEMM2: inter @ down_proj -> out_sorted ----------------
__global__ __launch_bounds__(256) void gemm2_kernel(
    const float* __restrict__ wd /*[E,I,H]*/) {
    int t = blockIdx.x;
    if (t >= g_ntiles) return;
    int e    = g_tile_e[t];
    int row0 = g_tile_r0[t];
    int rows = g_tile_rows[t];
    int h0   = blockIdx.y * BN2;

    __shared__ float As[BK][BM];
    __shared__ float Bs[BK][BN2];

    int tid  = threadIdx.x;
    int aRow = tid >> 1;
    int aK   = (tid & 1) * 4;
    int bK   = tid >> 5;                          // 0..7
    int bCol = (tid & 31) * 4;                    // 0..124
    int ty   = tid >> 4;
    int tx   = tid & 15;

    int arow_g = row0 + aRow;
    if (arow_g > NSLOT - 1) arow_g = NSLOT - 1;   // all inter rows are valid data
    const float* ap = g_inter + (size_t)arow_g * IDIM + aK;
    const float* bp = wd + ((size_t)e * IDIM + bK) * HDIM + h0 + bCol;

    float acc[8][8];
#pragma unroll
    for (int i = 0; i < 8; i++)
#pragma unroll
        for (int j = 0; j < 8; j++) acc[i][j] = 0.f;

    for (int k0 = 0; k0 < IDIM; k0 += BK) {
        float4 av = *(const float4*)(ap + k0);
        As[aK + 0][aRow] = av.x;
        As[aK + 1][aRow] = av.y;
        As[aK + 2][aRow] = av.z;
        As[aK + 3][aRow] = av.w;
        float4 bv = *(const float4*)(bp + (size_t)k0 * HDIM);
        Bs[bK][bCol + 0] = bv.x;
        Bs[bK][bCol + 1] = bv.y;
        Bs[bK][bCol + 2] = bv.z;
        Bs[bK][bCol + 3] = bv.w;
        __syncthreads();
#pragma unroll
        for (int kk = 0; kk < BK; kk++) {
            float a[8], b[8];
#pragma unroll
            for (int i = 0; i < 8; i++) a[i] = As[kk][ty * 8 + i];
#pragma unroll
            for (int j = 0; j < 8; j++) b[j] = Bs[kk][tx * 8 + j];
#pragma unroll
            for (int i = 0; i < 8; i++)
#pragma unroll
                for (int j = 0; j < 8; j++) acc[i][j] += a[i] * b[j];
        }
        __syncthreads();
    }

#pragma unroll
    for (int i = 0; i < 8; i++) {
        int r = ty * 8 + i;
        if (r < rows) {
            float* op = g_outs + (size_t)(row0 + r) * HDIM + h0 + tx * 8;
#pragma unroll
            for (int j = 0; j < 8; j++) op[j] = acc[i][j];
        }
    }
}

// -------------------- combine: weighted unroute (deterministic) -------------
__global__ void combine_kernel(const float* __restrict__ tw,
                               float* __restrict__ out) {
    const int HQ = HDIM / 4;
    int idx = blockIdx.x * blockDim.x + threadIdx.x;   // float4 index
    if (idx >= N_TOK * HQ) return;
    int n  = idx / HQ;
    int hq = idx - n * HQ;
    int p0 = g_slot2pos[n * TOPK + 0];
    int p1 = g_slot2pos[n * TOPK + 1];
    float w0 = tw[n * TOPK + 0];
    float w1 = tw[n * TOPK + 1];
    const float4* o4 = (const float4*)g_outs;
    float4 v0 = o4[(size_t)p0 * HQ + hq];
    float4 v1 = o4[(size_t)p1 * HQ + hq];
    float4 r;
    r.x = w0 * v0.x + w1 * v1.x;
    r.y = w0 * v0.y + w1 * v1.y;
    r.z = w0 * v0.z + w1 * v1.z;
    r.w = w0 * v0.w + w1 * v1.w;
    ((float4*)out)[idx] = r;
}

// -------------------- launch -------------------------------------------------
extern "C" void kernel_launch(void* const* d_in, const int* in_sizes, int n_in,
                              void* d_out, int out_size) {
    const float* x  = (const float*)d_in[0];   // [N, H]
    const int*   ti = (const int*)  d_in[1];   // [N, K]
    const float* tw = (const float*)d_in[2];   // [N, K]
    const float* gu = (const float*)d_in[3];   // [E, H, 2I]
    const float* dn = (const float*)d_in[4];   // [E, I, H]
    float* out = (float*)d_out;                // [N, H]

    route_kernel<<<1, 256>>>(ti);
    gemm1_kernel<<<dim3(MAXT, IDIM / BN1), 256>>>(x, gu);
    gemm2_kernel<<<dim3(MAXT, HDIM / BN2), 256>>>(dn);
    combine_kernel<<<(N_TOK * (HDIM / 4) + 255) / 256, 256>>>(tw, out);
}

// round 4
// speedup vs baseline: 7.1050x; 7.1050x over previous
#include <cuda_runtime.h>
#include <cuda.h>
#include <cuda_fp16.h>
#include <cstdint>

// ---------------- problem constants ----------------
#define N_TOK 8192
#define TOPK  2
#define NEXP  8
#define HDIM  2048
#define IDIM  1408
#define NSLOT (N_TOK * TOPK)           // 16384
#define BM    128
#define MAXT  (NSLOT / BM + NEXP)      // 136 worst-case M tiles

// ---------------- GEMM pipeline constants ----------------
#define KC      64                      // K elements per chunk (128 bytes fp16)
#define STAGES  4
#define A_BYTES (128 * KC * 2)          // 16384
#define B_BYTES (64 * KC * 2)           //  8192 per 64-row B half
#define STAGE_B (A_BYTES + 2 * B_BYTES) // 32768
#define SMEM_DYN (STAGES * STAGE_B + 1024)

// ---------------- scratch (static device globals) ----------------
__device__ __align__(16) __half g_ax   [(size_t)NSLOT * HDIM];            // sorted A, fp16
__device__ __align__(16) __half g_w1t  [(size_t)NEXP * 2 * IDIM * HDIM];  // [E][2816][2048]
__device__ __align__(16) __half g_w2t  [(size_t)NEXP * HDIM * IDIM];      // [E][2048][1408]
__device__ __align__(16) __half g_inter[(size_t)NSLOT * IDIM];            // fp16 SwiGLU out
__device__ __align__(16) float  g_outs [(size_t)NSLOT * HDIM];            // fp32 expert out
__device__ int g_pos2slot[NSLOT];
__device__ int g_slot2pos[NSLOT];
__device__ int g_tile_e[MAXT], g_tile_r0[MAXT], g_tile_rows[MAXT];
__device__ int g_ntiles;

// ---------------- PTX helpers ----------------
__device__ __forceinline__ uint32_t smem_u32(const void* p) {
    uint32_t a;
    asm("{ .reg .u64 t; cvta.to.shared.u64 t, %1; cvt.u32.u64 %0, t; }"
        : "=r"(a) : "l"(p));
    return a;
}
__device__ __forceinline__ void mbar_init(uint32_t a, uint32_t cnt) {
    asm volatile("mbarrier.init.shared.b64 [%0], %1;" :: "r"(a), "r"(cnt) : "memory");
}
__device__ __forceinline__ void mbar_expect(uint32_t a, uint32_t bytes) {
    asm volatile("mbarrier.arrive.expect_tx.shared.b64 _, [%0], %1;"
                 :: "r"(a), "r"(bytes) : "memory");
}
__device__ __forceinline__ void mbar_arrive(uint32_t a) {
    asm volatile("mbarrier.arrive.shared.b64 _, [%0];" :: "r"(a) : "memory");
}
__device__ __forceinline__ void mbar_wait(uint32_t a, uint32_t parity) {
    asm volatile(
        "{\n\t.reg .pred P;\n\t"
        "WL%=:\n\t"
        "mbarrier.try_wait.parity.acquire.cta.shared::cta.b64 P, [%0], %1, 0x989680;\n\t"
        "@P bra WD%=;\n\t"
        "bra WL%=;\n\t"
        "WD%=:\n\t}"
        :: "r"(a), "r"(parity) : "memory");
}
__device__ __forceinline__ void tma3d(uint32_t dst, const CUtensorMap* tm,
                                      int x, int y, int z, uint32_t mbar) {
    asm volatile(
        "cp.async.bulk.tensor.3d.shared::cta.global.tile.mbarrier::complete_tx::bytes "
        "[%0], [%1, {%2, %3, %4}], [%5];"
        :: "r"(dst), "l"(tm), "r"(x), "r"(y), "r"(z), "r"(mbar) : "memory");
}
__device__ __forceinline__ void ldsm4(uint32_t r[4], uint32_t addr) {
    asm volatile("ldmatrix.sync.aligned.m8n8.x4.shared.b16 {%0,%1,%2,%3}, [%4];"
                 : "=r"(r[0]), "=r"(r[1]), "=r"(r[2]), "=r"(r[3]) : "r"(addr));
}
__device__ __forceinline__ void mma16816(float c[4], const uint32_t a[4],
                                         uint32_t b0, uint32_t b1) {
    asm volatile(
        "mma.sync.aligned.m16n8k16.row.col.f32.f16.f16.f32 "
        "{%0,%1,%2,%3}, {%4,%5,%6,%7}, {%8,%9}, {%0,%1,%2,%3};"
        : "+f"(c[0]), "+f"(c[1]), "+f"(c[2]), "+f"(c[3])
        : "r"(a[0]), "r"(a[1]), "r"(a[2]), "r"(a[3]), "r"(b0), "r"(b1));
}
__device__ __forceinline__ uint32_t sw128(uint32_t off) {
    return off ^ ((off >> 3) & 0x70);
}

// ---------------- routing ----------------
__global__ void route_kernel(const int* __restrict__ topk_idx) {
    __shared__ int cnt[NEXP];
    __shared__ int cur[NEXP];
    int tid = threadIdx.x;
    if (tid < NEXP) cnt[tid] = 0;
    __syncthreads();
    for (int s = tid; s < NSLOT; s += blockDim.x)
        atomicAdd(&cnt[topk_idx[s]], 1);
    __syncthreads();
    if (tid == 0) {
        int off = 0, t = 0;
        for (int e = 0; e < NEXP; e++) {
            cur[e] = off;
            int c = cnt[e];
            for (int r = 0; r < c; r += BM) {
                g_tile_e[t] = e;
                g_tile_r0[t] = off + r;
                g_tile_rows[t] = (c - r < BM) ? (c - r) : BM;
                t++;
            }
            off += c;
        }
        g_ntiles = t;
    }
    __syncthreads();
    for (int s = tid; s < NSLOT; s += blockDim.x) {
        int p = atomicAdd(&cur[topk_idx[s]], 1);
        g_pos2slot[p] = s;
        g_slot2pos[s] = p;
    }
}

// ---------------- gather + fp16 convert of A ----------------
__global__ void gather_x_kernel(const float* __restrict__ x) {
    int pos = blockIdx.x;
    int token = g_pos2slot[pos] / TOPK;
    const float4* src = (const float4*)(x + (size_t)token * HDIM);
    uint2* dst = (uint2*)(g_ax + (size_t)pos * HDIM);
    for (int c = threadIdx.x; c < HDIM / 4; c += blockDim.x) {
        float4 v = src[c];
        __half2 a = __floats2half2_rn(v.x, v.y);
        __half2 b = __floats2half2_rn(v.z, v.w);
        uint2 u;
        u.x = *(uint32_t*)&a;
        u.y = *(uint32_t*)&b;
        dst[c] = u;
    }
}

// ---------------- weight transpose + fp16 convert ----------------
__global__ void transpose_w1_kernel(const float* __restrict__ w) {
    __shared__ float t[32][33];
    int e = blockIdx.z;
    int n0 = blockIdx.x * 32;   // 2I dim
    int k0 = blockIdx.y * 32;   // H dim
    int tx = threadIdx.x, ty = threadIdx.y;
    const float* src = w + (size_t)e * HDIM * (2 * IDIM);
#pragma unroll
    for (int i = 0; i < 32; i += 8)
        t[ty + i][tx] = src[(size_t)(k0 + ty + i) * (2 * IDIM) + n0 + tx];
    __syncthreads();
    __half* dst = g_w1t + (size_t)e * (2 * IDIM) * HDIM;
#pragma unroll
    for (int i = 0; i < 32; i += 8)
        dst[(size_t)(n0 + ty + i) * HDIM + k0 + tx] = __float2half(t[tx][ty + i]);
}
__global__ void transpose_w2_kernel(const float* __restrict__ w) {
    __shared__ float t[32][33];
    int e = blockIdx.z;
    int h0 = blockIdx.x * 32;   // H dim
    int i0 = blockIdx.y * 32;   // I dim
    int tx = threadIdx.x, ty = threadIdx.y;
    const float* src = w + (size_t)e * IDIM * HDIM;
#pragma unroll
    for (int i = 0; i < 32; i += 8)
        t[ty + i][tx] = src[(size_t)(i0 + ty + i) * HDIM + h0 + tx];
    __syncthreads();
    __half* dst = g_w2t + (size_t)e * HDIM * IDIM;
#pragma unroll
    for (int i = 0; i < 32; i += 8)
        dst[(size_t)(h0 + ty + i) * IDIM + i0 + tx] = __float2half(t[tx][ty + i]);
}

// ---------------- HMMA mainloop: M=128 x N=(64+64), TMA pipelined ----------
// acc[mt][nt][frag]: mt = 16-row tile (2), nt = 8-col tile (0-3 half0, 4-7 half1)
__device__ __forceinline__ void hmma_mainloop(
    uint32_t sb, const CUtensorMap* tA, const CUtensorMap* tB,
    int row0, int y0, int y1, int ez, int nchunks, float acc[2][8][4])
{
    __shared__ __align__(8) unsigned long long mbar[2 * STAGES];
    int tid = threadIdx.x;
    uint32_t fb = smem_u32(&mbar[0]);
    uint32_t eb = smem_u32(&mbar[STAGES]);
    if (tid == 0) {
        for (int s = 0; s < STAGES; s++) {
            mbar_init(fb + 8u * s, 1);
            mbar_init(eb + 8u * s, 256);
        }
    }
    __syncthreads();
    if (tid == 0) {
        int npre = (STAGES < nchunks) ? STAGES : nchunks;
        for (int c = 0; c < npre; c++) {
            uint32_t st = sb + c * STAGE_B;
            mbar_expect(fb + 8u * c, STAGE_B);
            tma3d(st,                       tA, c * KC, row0, 0,  fb + 8u * c);
            tma3d(st + A_BYTES,             tB, c * KC, y0,   ez, fb + 8u * c);
            tma3d(st + A_BYTES + B_BYTES,   tB, c * KC, y1,   ez, fb + 8u * c);
        }
    }
    int lane = tid & 31, warp = tid >> 5;
    int wm = warp >> 1, wn = warp & 1;               // 4m x 2n warp grid
    int aRow = wm * 32 + (lane & 15);                // + mt*16
    int aKb  = (lane >> 4) << 4;                     // + ks*32
    int bRow = wn * 32 + (lane & 7) + ((lane >> 4) << 3);  // + pp*16
    int bKb  = ((lane >> 3) & 1) << 4;               // + ks*32

    for (int c = 0; c < nchunks; c++) {
        int s = c & (STAGES - 1);
        uint32_t st = sb + s * STAGE_B;
        mbar_wait(fb + 8u * s, (c >> 2) & 1);
        uint32_t aB = st, b0B = st + A_BYTES, b1B = st + A_BYTES + B_BYTES;
#pragma unroll
        for (int ks = 0; ks < KC / 16; ks++) {
            uint32_t a[2][4];
#pragma unroll
            for (int mt = 0; mt < 2; mt++) {
                uint32_t off = (uint32_t)(aRow + mt * 16) * 128 + aKb + ks * 32;
                ldsm4(a[mt], aB + sw128(off));
            }
#pragma unroll
            for (int half = 0; half < 2; half++) {
                uint32_t base = half ? b1B : b0B;
#pragma unroll
                for (int pp = 0; pp < 2; pp++) {
                    uint32_t off = (uint32_t)(bRow + pp * 16) * 128 + bKb + ks * 32;
                    uint32_t b[4];
                    ldsm4(b, base + sw128(off));
                    int nt = half * 4 + pp * 2;
                    mma16816(acc[0][nt],     a[0], b[0], b[1]);
                    mma16816(acc[0][nt + 1], a[0], b[2], b[3]);
                    mma16816(acc[1][nt],     a[1], b[0], b[1]);
                    mma16816(acc[1][nt + 1], a[1], b[2], b[3]);
                }
            }
        }
        mbar_arrive(eb + 8u * s);
        if (tid == 0 && c + STAGES < nchunks) {
            mbar_wait(eb + 8u * s, (c >> 2) & 1);
            int cn = c + STAGES;
            mbar_expect(fb + 8u * s, STAGE_B);
            tma3d(st,                     tA, cn * KC, row0, 0,  fb + 8u * s);
            tma3d(st + A_BYTES,           tB, cn * KC, y0,   ez, fb + 8u * s);
            tma3d(st + A_BYTES + B_BYTES, tB, cn * KC, y1,   ez, fb + 8u * s);
        }
    }
}

// ---------------- GEMM1: A_sorted @ w1t (gate+up) + fused SwiGLU ------------
__global__ __launch_bounds__(256, 1) void gemm1_tc(
    const __grid_constant__ CUtensorMap tA,
    const __grid_constant__ CUtensorMap tB)
{
    int t = blockIdx.y;
    if (t >= g_ntiles) return;
    int e = g_tile_e[t], row0 = g_tile_r0[t], rows = g_tile_rows[t];
    int c0 = blockIdx.x * 64;
    extern __shared__ __align__(1024) char dsm[];
    uint32_t sb = (smem_u32(dsm) + 1023u) & ~1023u;

    float acc[2][8][4];
#pragma unroll
    for (int i = 0; i < 2; i++)
#pragma unroll
        for (int j = 0; j < 8; j++)
#pragma unroll
            for (int q = 0; q < 4; q++) acc[i][j][q] = 0.f;

    hmma_mainloop(sb, &tA, &tB, row0, c0, IDIM + c0, e, HDIM / KC, acc);

    int lane = threadIdx.x & 31, warp = threadIdx.x >> 5;
    int wm = warp >> 1, wn = warp & 1;
#pragma unroll
    for (int mt = 0; mt < 2; mt++) {
#pragma unroll
        for (int nt = 0; nt < 4; nt++) {
            int col = c0 + wn * 32 + nt * 8 + 2 * (lane & 3);
            int r_lo = wm * 32 + mt * 16 + (lane >> 2);
            float g0 = acc[mt][nt][0], g1 = acc[mt][nt][1];
            float u0 = acc[mt][nt + 4][0], u1 = acc[mt][nt + 4][1];
            if (r_lo < rows) {
                float o0 = u0 * (g0 / (1.f + __expf(-g0)));
                float o1 = u1 * (g1 / (1.f + __expf(-g1)));
                __half2 p = __floats2half2_rn(o0, o1);
                *(__half2*)(g_inter + (size_t)(row0 + r_lo) * IDIM + col) = p;
            }
            int r_hi = r_lo + 8;
            g0 = acc[mt][nt][2]; g1 = acc[mt][nt][3];
            u0 = acc[mt][nt + 4][2]; u1 = acc[mt][nt + 4][3];
            if (r_hi < rows) {
                float o0 = u0 * (g0 / (1.f + __expf(-g0)));
                float o1 = u1 * (g1 / (1.f + __expf(-g1)));
                __half2 p = __floats2half2_rn(o0, o1);
                *(__half2*)(g_inter + (size_t)(row0 + r_hi) * IDIM + col) = p;
            }
        }
    }
}

// ---------------- GEMM2: g_inter @ w2t -> g_outs ----------------------------
__global__ __launch_bounds__(256, 1) void gemm2_tc(
    const __grid_constant__ CUtensorMap tA,
    const __grid_constant__ CUtensorMap tB)
{
    int t = blockIdx.y;
    if (t >= g_ntiles) return;
    int e = g_tile_e[t], row0 = g_tile_r0[t], rows = g_tile_rows[t];
    int n0 = blockIdx.x * 128;
    extern __shared__ __align__(1024) char dsm[];
    uint32_t sb = (smem_u32(dsm) + 1023u) & ~1023u;

    float acc[2][8][4];
#pragma unroll
    for (int i = 0; i < 2; i++)
#pragma unroll
        for (int j = 0; j < 8; j++)
#pragma unroll
            for (int q = 0; q < 4; q++) acc[i][j][q] = 0.f;

    hmma_mainloop(sb, &tA, &tB, row0, n0, n0 + 64, e, IDIM / KC, acc);

    int lane = threadIdx.x & 31, warp = threadIdx.x >> 5;
    int wm = warp >> 1, wn = warp & 1;
#pragma unroll
    for (int mt = 0; mt < 2; mt++) {
#pragma unroll
        for (int nt = 0; nt < 8; nt++) {
            int colh = (nt < 4) ? (wn * 32 + nt * 8) : (64 + wn * 32 + (nt - 4) * 8);
            int col = n0 + colh + 2 * (lane & 3);
            int r_lo = wm * 32 + mt * 16 + (lane >> 2);
            if (r_lo < rows) {
                float2 v = make_float2(acc[mt][nt][0], acc[mt][nt][1]);
                *(float2*)(g_outs + (size_t)(row0 + r_lo) * HDIM + col) = v;
            }
            int r_hi = r_lo + 8;
            if (r_hi < rows) {
                float2 v = make_float2(acc[mt][nt][2], acc[mt][nt][3]);
                *(float2*)(g_outs + (size_t)(row0 + r_hi) * HDIM + col) = v;
            }
        }
    }
}

// ---------------- combine: weighted unroute ----------------
__global__ void combine_kernel(const float* __restrict__ tw,
                               float* __restrict__ out) {
    const int HQ = HDIM / 4;
    int idx = blockIdx.x * blockDim.x + threadIdx.x;
    if (idx >= N_TOK * HQ) return;
    int n = idx / HQ;
    int hq = idx - n * HQ;
    int p0 = g_slot2pos[n * TOPK + 0];
    int p1 = g_slot2pos[n * TOPK + 1];
    float w0 = tw[n * TOPK + 0];
    float w1 = tw[n * TOPK + 1];
    const float4* o4 = (const float4*)g_outs;
    float4 v0 = o4[(size_t)p0 * HQ + hq];
    float4 v1 = o4[(size_t)p1 * HQ + hq];
    float4 r;
    r.x = w0 * v0.x + w1 * v1.x;
    r.y = w0 * v0.y + w1 * v1.y;
    r.z = w0 * v0.z + w1 * v1.z;
    r.w = w0 * v0.w + w1 * v1.w;
    ((float4*)out)[idx] = r;
}

// ---------------- host ----------------
typedef CUresult (*encfn_t)(CUtensorMap*, CUtensorMapDataType, cuuint32_t, void*,
                            const cuuint64_t*, const cuuint64_t*, const cuuint32_t*,
                            const cuuint32_t*, CUtensorMapInterleave, CUtensorMapSwizzle,
                            CUtensorMapL2promotion, CUtensorMapFloatOOBfill);

static void enc_f16(encfn_t fn, CUtensorMap* m, void* p,
                    unsigned long long d0, unsigned long long d1, unsigned long long d2,
                    unsigned long long s1, unsigned long long s2, unsigned box1) {
    cuuint64_t dims[3] = {d0, d1, d2};
    cuuint64_t str[2]  = {s1, s2};
    cuuint32_t box[3]  = {KC, box1, 1};
    cuuint32_t es[3]   = {1, 1, 1};
    fn(m, CU_TENSOR_MAP_DATA_TYPE_FLOAT16, 3, p, dims, str, box, es,
       CU_TENSOR_MAP_INTERLEAVE_NONE, CU_TENSOR_MAP_SWIZZLE_128B,
       CU_TENSOR_MAP_L2_PROMOTION_L2_128B, CU_TENSOR_MAP_FLOAT_OOB_FILL_NONE);
}

extern "C" void kernel_launch(void* const* d_in, const int* in_sizes, int n_in,
                              void* d_out, int out_size) {
    const float* x  = (const float*)d_in[0];
    const int*   ti = (const int*)  d_in[1];
    const float* tw = (const float*)d_in[2];
    const float* gu = (const float*)d_in[3];
    const float* dn = (const float*)d_in[4];
    float* out = (float*)d_out;

    void* fp = nullptr;
    cudaDriverEntryPointQueryResult qr;
    cudaGetDriverEntryPointByVersion("cuTensorMapEncodeTiled", &fp, 12000,
                                     cudaEnableDefault, &qr);
    encfn_t fn = (encfn_t)fp;

    void *pax, *pw1, *pw2, *pint;
    cudaGetSymbolAddress(&pax,  g_ax);
    cudaGetSymbolAddress(&pw1,  g_w1t);
    cudaGetSymbolAddress(&pw2,  g_w2t);
    cudaGetSymbolAddress(&pint, g_inter);

    CUtensorMap tA1, tB1, tA2, tB2;
    // A1: g_ax [16384, 2048] fp16, box {64,128}
    enc_f16(fn, &tA1, pax, HDIM, NSLOT, 1,
            (unsigned long long)HDIM * 2, (unsigned long long)HDIM * 2 * NSLOT, 128);
    // B1: g_w1t [E][2816][2048] fp16, box {64,64}
    enc_f16(fn, &tB1, pw1, HDIM, 2 * IDIM, NEXP,
            (unsigned long long)HDIM * 2, (unsigned long long)HDIM * 2 * 2 * IDIM, 64);
    // A2: g_inter [16384, 1408] fp16, box {64,128}
    enc_f16(fn, &tA2, pint, IDIM, NSLOT, 1,
            (unsigned long long)IDIM * 2, (unsigned long long)IDIM * 2 * NSLOT, 128);
    // B2: g_w2t [E][2048][1408] fp16, box {64,64}
    enc_f16(fn, &tB2, pw2, IDIM, HDIM, NEXP,
            (unsigned long long)IDIM * 2, (unsigned long long)IDIM * 2 * HDIM, 64);

    cudaFuncSetAttribute(gemm1_tc, cudaFuncAttributeMaxDynamicSharedMemorySize, SMEM_DYN);
    cudaFuncSetAttribute(gemm2_tc, cudaFuncAttributeMaxDynamicSharedMemorySize, SMEM_DYN);

    route_kernel<<<1, 256>>>(ti);
    gather_x_kernel<<<NSLOT, 256>>>(x);
    transpose_w1_kernel<<<dim3(2 * IDIM / 32, HDIM / 32, NEXP), dim3(32, 8)>>>(gu);
    transpose_w2_kernel<<<dim3(HDIM / 32, IDIM / 32, NEXP), dim3(32, 8)>>>(dn);
    gemm1_tc<<<dim3(IDIM / 64, MAXT), 256, SMEM_DYN>>>(tA1, tB1);
    gemm2_tc<<<dim3(HDIM / 128, MAXT), 256, SMEM_DYN>>>(tA2, tB2);
    combine_kernel<<<(N_TOK * (HDIM / 4) + 255) / 256, 256>>>(tw, out);
}

// round 5
// speedup vs baseline: 7.6338x; 1.0744x over previous
#include <cuda_runtime.h>
#include <cuda.h>
#include <cuda_fp16.h>
#include <cstdint>

// ---------------- problem constants ----------------
#define N_TOK 8192
#define TOPK  2
#define NEXP  8
#define HDIM  2048
#define IDIM  1408
#define NSLOT (N_TOK * TOPK)           // 16384
#define BM    128
#define MAXT  (NSLOT / BM + NEXP)      // 136 worst-case M tiles

// ---------------- GEMM pipeline constants ----------------
#define KC      64                      // K elements per chunk (128 bytes fp16)
#define STAGES  4
#define A_BYTES (128 * KC * 2)          // 16384
#define B_HALF  (128 * KC * 2)          // 16384 per 128-row B half
#define STAGE_B (A_BYTES + 2 * B_HALF)  // 49152
#define SMEM_DYN (STAGES * STAGE_B + 1024)

// ---------------- scratch (static device globals) ----------------
__device__ __align__(16) __half g_ax   [(size_t)NSLOT * HDIM];            // sorted A, fp16
__device__ __align__(16) __half g_w1t  [(size_t)NEXP * 2 * IDIM * HDIM];  // [E][2816][2048]
__device__ __align__(16) __half g_w2t  [(size_t)NEXP * HDIM * IDIM];      // [E][2048][1408]
__device__ __align__(16) __half g_inter[(size_t)NSLOT * IDIM];            // fp16 SwiGLU out
__device__ __align__(16) float  g_outs [(size_t)NSLOT * HDIM];            // fp32 expert out
__device__ int g_pos2slot[NSLOT];
__device__ int g_slot2pos[NSLOT];
__device__ int g_tile_e[MAXT], g_tile_r0[MAXT], g_tile_rows[MAXT];
__device__ int g_ntiles;

// ---------------- PTX helpers ----------------
__device__ __forceinline__ uint32_t smem_u32(const void* p) {
    uint32_t a;
    asm("{ .reg .u64 t; cvta.to.shared.u64 t, %1; cvt.u32.u64 %0, t; }"
        : "=r"(a) : "l"(p));
    return a;
}
__device__ __forceinline__ void mbar_init(uint32_t a, uint32_t cnt) {
    asm volatile("mbarrier.init.shared.b64 [%0], %1;" :: "r"(a), "r"(cnt) : "memory");
}
__device__ __forceinline__ void mbar_expect(uint32_t a, uint32_t bytes) {
    asm volatile("mbarrier.arrive.expect_tx.shared.b64 _, [%0], %1;"
                 :: "r"(a), "r"(bytes) : "memory");
}
__device__ __forceinline__ void mbar_arrive(uint32_t a) {
    asm volatile("mbarrier.arrive.shared.b64 _, [%0];" :: "r"(a) : "memory");
}
__device__ __forceinline__ void mbar_wait(uint32_t a, uint32_t parity) {
    asm volatile(
        "{\n\t.reg .pred P;\n\t"
        "WL%=:\n\t"
        "mbarrier.try_wait.parity.acquire.cta.shared::cta.b64 P, [%0], %1, 0x989680;\n\t"
        "@P bra WD%=;\n\t"
        "bra WL%=;\n\t"
        "WD%=:\n\t}"
        :: "r"(a), "r"(parity) : "memory");
}
__device__ __forceinline__ void tma3d(uint32_t dst, const CUtensorMap* tm,
                                      int x, int y, int z, uint32_t mbar) {
    asm volatile(
        "cp.async.bulk.tensor.3d.shared::cta.global.tile.mbarrier::complete_tx::bytes "
        "[%0], [%1, {%2, %3, %4}], [%5];"
        :: "r"(dst), "l"(tm), "r"(x), "r"(y), "r"(z), "r"(mbar) : "memory");
}
__device__ __forceinline__ void ldsm4(uint32_t r[4], uint32_t addr) {
    asm volatile("ldmatrix.sync.aligned.m8n8.x4.shared.b16 {%0,%1,%2,%3}, [%4];"
                 : "=r"(r[0]), "=r"(r[1]), "=r"(r[2]), "=r"(r[3]) : "r"(addr));
}
__device__ __forceinline__ void mma16816(float c[4], const uint32_t a[4],
                                         uint32_t b0, uint32_t b1) {
    asm volatile(
        "mma.sync.aligned.m16n8k16.row.col.f32.f16.f16.f32 "
        "{%0,%1,%2,%3}, {%4,%5,%6,%7}, {%8,%9}, {%0,%1,%2,%3};"
        : "+f"(c[0]), "+f"(c[1]), "+f"(c[2]), "+f"(c[3])
        : "r"(a[0]), "r"(a[1]), "r"(a[2]), "r"(a[3]), "r"(b0), "r"(b1));
}
__device__ __forceinline__ uint32_t sw128(uint32_t off) {
    return off ^ ((off >> 3) & 0x70);
}

// ---------------- routing ----------------
__global__ void route_kernel(const int* __restrict__ topk_idx) {
    __shared__ int cnt[NEXP];
    __shared__ int cur[NEXP];
    int tid = threadIdx.x;
    if (tid < NEXP) cnt[tid] = 0;
    __syncthreads();
    for (int s = tid; s < NSLOT; s += blockDim.x)
        atomicAdd(&cnt[topk_idx[s]], 1);
    __syncthreads();
    if (tid == 0) {
        int off = 0, t = 0;
        for (int e = 0; e < NEXP; e++) {
            cur[e] = off;
            int c = cnt[e];
            for (int r = 0; r < c; r += BM) {
                g_tile_e[t] = e;
                g_tile_r0[t] = off + r;
                g_tile_rows[t] = (c - r < BM) ? (c - r) : BM;
                t++;
            }
            off += c;
        }
        g_ntiles = t;
    }
    __syncthreads();
    for (int s = tid; s < NSLOT; s += blockDim.x) {
        int p = atomicAdd(&cur[topk_idx[s]], 1);
        g_pos2slot[p] = s;
        g_slot2pos[s] = p;
    }
}

// ---------------- gather + fp16 convert of A ----------------
__global__ void gather_x_kernel(const float* __restrict__ x) {
    int pos = blockIdx.x;
    int token = g_pos2slot[pos] / TOPK;
    const float4* src = (const float4*)(x + (size_t)token * HDIM);
    uint2* dst = (uint2*)(g_ax + (size_t)pos * HDIM);
    for (int c = threadIdx.x; c < HDIM / 4; c += blockDim.x) {
        float4 v = src[c];
        __half2 a = __floats2half2_rn(v.x, v.y);
        __half2 b = __floats2half2_rn(v.z, v.w);
        uint2 u;
        u.x = *(uint32_t*)&a;
        u.y = *(uint32_t*)&b;
        dst[c] = u;
    }
}

// ---------------- weight transpose + fp16 convert ----------------
__global__ void transpose_w1_kernel(const float* __restrict__ w) {
    __shared__ float t[32][33];
    int e = blockIdx.z;
    int n0 = blockIdx.x * 32;   // 2I dim
    int k0 = blockIdx.y * 32;   // H dim
    int tx = threadIdx.x, ty = threadIdx.y;
    const float* src = w + (size_t)e * HDIM * (2 * IDIM);
#pragma unroll
    for (int i = 0; i < 32; i += 8)
        t[ty + i][tx] = src[(size_t)(k0 + ty + i) * (2 * IDIM) + n0 + tx];
    __syncthreads();
    __half* dst = g_w1t + (size_t)e * (2 * IDIM) * HDIM;
#pragma unroll
    for (int i = 0; i < 32; i += 8)
        dst[(size_t)(n0 + ty + i) * HDIM + k0 + tx] = __float2half(t[tx][ty + i]);
}
__global__ void transpose_w2_kernel(const float* __restrict__ w) {
    __shared__ float t[32][33];
    int e = blockIdx.z;
    int h0 = blockIdx.x * 32;   // H dim
    int i0 = blockIdx.y * 32;   // I dim
    int tx = threadIdx.x, ty = threadIdx.y;
    const float* src = w + (size_t)e * IDIM * HDIM;
#pragma unroll
    for (int i = 0; i < 32; i += 8)
        t[ty + i][tx] = src[(size_t)(i0 + ty + i) * HDIM + h0 + tx];
    __syncthreads();
    __half* dst = g_w2t + (size_t)e * HDIM * IDIM;
#pragma unroll
    for (int i = 0; i < 32; i += 8)
        dst[(size_t)(h0 + ty + i) * IDIM + i0 + tx] = __float2half(t[tx][ty + i]);
}

// ---------------- HMMA mainloop: M=128 x N=(128+128), TMA pipelined ---------
// Warp grid 2m x 4n; warp tile 64M x (32+32)N.
// acc[mt][nt][frag]: mt = 16-row tile (4), nt 0-3 = half0 cols, 4-7 = half1.
__device__ __forceinline__ void hmma_mainloop(
    uint32_t sb, const CUtensorMap* tA, const CUtensorMap* tB,
    int row0, int y0, int y1, int ez, int nchunks, float acc[4][8][4])
{
    __shared__ __align__(8) unsigned long long mbar[2 * STAGES];
    int tid = threadIdx.x;
    uint32_t fb = smem_u32(&mbar[0]);
    uint32_t eb = smem_u32(&mbar[STAGES]);
    if (tid == 0) {
        for (int s = 0; s < STAGES; s++) {
            mbar_init(fb + 8u * s, 1);
            mbar_init(eb + 8u * s, 256);
        }
    }
    __syncthreads();
    if (tid == 0) {
        int npre = (STAGES < nchunks) ? STAGES : nchunks;
        for (int c = 0; c < npre; c++) {
            uint32_t st = sb + c * STAGE_B;
            mbar_expect(fb + 8u * c, STAGE_B);
            tma3d(st,                      tA, c * KC, row0, 0,  fb + 8u * c);
            tma3d(st + A_BYTES,            tB, c * KC, y0,   ez, fb + 8u * c);
            tma3d(st + A_BYTES + B_HALF,   tB, c * KC, y1,   ez, fb + 8u * c);
        }
    }
    int lane = tid & 31, warp = tid >> 5;
    int wm = warp >> 2, wn = warp & 3;               // 2m x 4n warp grid
    int aRow = wm * 64 + (lane & 15);                // + mt*16
    int aKb  = (lane >> 4) << 4;                     // + ks*32
    int bRow = wn * 32 + (lane & 7) + ((lane >> 4) << 3);  // + pp*16
    int bKb  = ((lane >> 3) & 1) << 4;               // + ks*32

    for (int c = 0; c < nchunks; c++) {
        int s = c & (STAGES - 1);
        uint32_t st = sb + s * STAGE_B;
        mbar_wait(fb + 8u * s, (c >> 2) & 1);
        uint32_t aB = st, b0B = st + A_BYTES, b1B = st + A_BYTES + B_HALF;
#pragma unroll
        for (int ks = 0; ks < KC / 16; ks++) {
            uint32_t a[4][4];
#pragma unroll
            for (int mt = 0; mt < 4; mt++) {
                uint32_t off = (uint32_t)(aRow + mt * 16) * 128 + aKb + ks * 32;
                ldsm4(a[mt], aB + sw128(off));
            }
#pragma unroll
            for (int half = 0; half < 2; half++) {
                uint32_t base = half ? b1B : b0B;
#pragma unroll
                for (int pp = 0; pp < 2; pp++) {
                    uint32_t off = (uint32_t)(bRow + pp * 16) * 128 + bKb + ks * 32;
                    uint32_t b[4];
                    ldsm4(b, base + sw128(off));
                    int nt = half * 4 + pp * 2;
#pragma unroll
                    for (int mt = 0; mt < 4; mt++) {
                        mma16816(acc[mt][nt],     a[mt], b[0], b[1]);
                        mma16816(acc[mt][nt + 1], a[mt], b[2], b[3]);
                    }
                }
            }
        }
        mbar_arrive(eb + 8u * s);
        if (tid == 0 && c + STAGES < nchunks) {
            mbar_wait(eb + 8u * s, (c >> 2) & 1);
            int cn = c + STAGES;
            mbar_expect(fb + 8u * s, STAGE_B);
            tma3d(st,                    tA, cn * KC, row0, 0,  fb + 8u * s);
            tma3d(st + A_BYTES,          tB, cn * KC, y0,   ez, fb + 8u * s);
            tma3d(st + A_BYTES + B_HALF, tB, cn * KC, y1,   ez, fb + 8u * s);
        }
    }
}

// ---------------- GEMM1: A_sorted @ w1t (gate+up) + fused SwiGLU ------------
// N tile: 128 gate cols (c0..) paired with 128 up cols (IDIM+c0..)
__global__ __launch_bounds__(256, 1) void gemm1_tc(
    const __grid_constant__ CUtensorMap tA,
    const __grid_constant__ CUtensorMap tB)
{
    int t = blockIdx.y;
    if (t >= g_ntiles) return;
    int e = g_tile_e[t], row0 = g_tile_r0[t], rows = g_tile_rows[t];
    int c0 = blockIdx.x * 128;
    extern __shared__ __align__(1024) char dsm[];
    uint32_t sb = (smem_u32(dsm) + 1023u) & ~1023u;

    float acc[4][8][4];
#pragma unroll
    for (int i = 0; i < 4; i++)
#pragma unroll
        for (int j = 0; j < 8; j++)
#pragma unroll
            for (int q = 0; q < 4; q++) acc[i][j][q] = 0.f;

    hmma_mainloop(sb, &tA, &tB, row0, c0, IDIM + c0, e, HDIM / KC, acc);

    int lane = threadIdx.x & 31, warp = threadIdx.x >> 5;
    int wm = warp >> 2, wn = warp & 3;
#pragma unroll
    for (int mt = 0; mt < 4; mt++) {
#pragma unroll
        for (int nt = 0; nt < 4; nt++) {
            int col = c0 + wn * 32 + nt * 8 + 2 * (lane & 3);
            int r_lo = wm * 64 + mt * 16 + (lane >> 2);
            float g0 = acc[mt][nt][0], g1 = acc[mt][nt][1];
            float u0 = acc[mt][nt + 4][0], u1 = acc[mt][nt + 4][1];
            if (r_lo < rows) {
                float o0 = u0 * (g0 / (1.f + __expf(-g0)));
                float o1 = u1 * (g1 / (1.f + __expf(-g1)));
                __half2 p = __floats2half2_rn(o0, o1);
                *(__half2*)(g_inter + (size_t)(row0 + r_lo) * IDIM + col) = p;
            }
            int r_hi = r_lo + 8;
            g0 = acc[mt][nt][2]; g1 = acc[mt][nt][3];
            u0 = acc[mt][nt + 4][2]; u1 = acc[mt][nt + 4][3];
            if (r_hi < rows) {
                float o0 = u0 * (g0 / (1.f + __expf(-g0)));
                float o1 = u1 * (g1 / (1.f + __expf(-g1)));
                __half2 p = __floats2half2_rn(o0, o1);
                *(__half2*)(g_inter + (size_t)(row0 + r_hi) * IDIM + col) = p;
            }
        }
    }
}

// ---------------- GEMM2: g_inter @ w2t -> g_outs ----------------------------
__global__ __launch_bounds__(256, 1) void gemm2_tc(
    const __grid_constant__ CUtensorMap tA,
    const __grid_constant__ CUtensorMap tB)
{
    int t = blockIdx.y;
    if (t >= g_ntiles) return;
    int e = g_tile_e[t], row0 = g_tile_r0[t], rows = g_tile_rows[t];
    int n0 = blockIdx.x * 256;
    extern __shared__ __align__(1024) char dsm[];
    uint32_t sb = (smem_u32(dsm) + 1023u) & ~1023u;

    float acc[4][8][4];
#pragma unroll
    for (int i = 0; i < 4; i++)
#pragma unroll
        for (int j = 0; j < 8; j++)
#pragma unroll
            for (int q = 0; q < 4; q++) acc[i][j][q] = 0.f;

    hmma_mainloop(sb, &tA, &tB, row0, n0, n0 + 128, e, IDIM / KC, acc);

    int lane = threadIdx.x & 31, warp = threadIdx.x >> 5;
    int wm = warp >> 2, wn = warp & 3;
#pragma unroll
    for (int mt = 0; mt < 4; mt++) {
#pragma unroll
        for (int nt = 0; nt < 8; nt++) {
            int colh = (nt < 4) ? (wn * 32 + nt * 8) : (128 + wn * 32 + (nt - 4) * 8);
            int col = n0 + colh + 2 * (lane & 3);
            int r_lo = wm * 64 + mt * 16 + (lane >> 2);
            if (r_lo < rows) {
                float2 v = make_float2(acc[mt][nt][0], acc[mt][nt][1]);
                *(float2*)(g_outs + (size_t)(row0 + r_lo) * HDIM + col) = v;
            }
            int r_hi = r_lo + 8;
            if (r_hi < rows) {
                float2 v = make_float2(acc[mt][nt][2], acc[mt][nt][3]);
                *(float2*)(g_outs + (size_t)(row0 + r_hi) * HDIM + col) = v;
            }
        }
    }
}

// ---------------- combine: weighted unroute ----------------
__global__ void combine_kernel(const float* __restrict__ tw,
                               float* __restrict__ out) {
    const int HQ = HDIM / 4;
    int idx = blockIdx.x * blockDim.x + threadIdx.x;
    if (idx >= N_TOK * HQ) return;
    int n = idx / HQ;
    int hq = idx - n * HQ;
    int p0 = g_slot2pos[n * TOPK + 0];
    int p1 = g_slot2pos[n * TOPK + 1];
    float w0 = tw[n * TOPK + 0];
    float w1 = tw[n * TOPK + 1];
    const float4* o4 = (const float4*)g_outs;
    float4 v0 = o4[(size_t)p0 * HQ + hq];
    float4 v1 = o4[(size_t)p1 * HQ + hq];
    float4 r;
    r.x = w0 * v0.x + w1 * v1.x;
    r.y = w0 * v0.y + w1 * v1.y;
    r.z = w0 * v0.z + w1 * v1.z;
    r.w = w0 * v0.w + w1 * v1.w;
    ((float4*)out)[idx] = r;
}

// ---------------- host ----------------
typedef CUresult (*encfn_t)(CUtensorMap*, CUtensorMapDataType, cuuint32_t, void*,
                            const cuuint64_t*, const cuuint64_t*, const cuuint32_t*,
                            const cuuint32_t*, CUtensorMapInterleave, CUtensorMapSwizzle,
                            CUtensorMapL2promotion, CUtensorMapFloatOOBfill);

static void enc_f16(encfn_t fn, CUtensorMap* m, void* p,
                    unsigned long long d0, unsigned long long d1, unsigned long long d2,
                    unsigned long long s1, unsigned long long s2, unsigned box1) {
    cuuint64_t dims[3] = {d0, d1, d2};
    cuuint64_t str[2]  = {s1, s2};
    cuuint32_t box[3]  = {KC, box1, 1};
    cuuint32_t es[3]   = {1, 1, 1};
    fn(m, CU_TENSOR_MAP_DATA_TYPE_FLOAT16, 3, p, dims, str, box, es,
       CU_TENSOR_MAP_INTERLEAVE_NONE, CU_TENSOR_MAP_SWIZZLE_128B,
       CU_TENSOR_MAP_L2_PROMOTION_L2_128B, CU_TENSOR_MAP_FLOAT_OOB_FILL_NONE);
}

extern "C" void kernel_launch(void* const* d_in, const int* in_sizes, int n_in,
                              void* d_out, int out_size) {
    const float* x  = (const float*)d_in[0];
    const int*   ti = (const int*)  d_in[1];
    const float* tw = (const float*)d_in[2];
    const float* gu = (const float*)d_in[3];
    const float* dn = (const float*)d_in[4];
    float* out = (float*)d_out;

    void* fp = nullptr;
    cudaDriverEntryPointQueryResult qr;
    cudaGetDriverEntryPointByVersion("cuTensorMapEncodeTiled", &fp, 12000,
                                     cudaEnableDefault, &qr);
    encfn_t fn = (encfn_t)fp;

    void *pax, *pw1, *pw2, *pint;
    cudaGetSymbolAddress(&pax,  g_ax);
    cudaGetSymbolAddress(&pw1,  g_w1t);
    cudaGetSymbolAddress(&pw2,  g_w2t);
    cudaGetSymbolAddress(&pint, g_inter);

    CUtensorMap tA1, tB1, tA2, tB2;
    // A1: g_ax [16384, 2048] fp16, box {64,128}
    enc_f16(fn, &tA1, pax, HDIM, NSLOT, 1,
            (unsigned long long)HDIM * 2, (unsigned long long)HDIM * 2 * NSLOT, 128);
    // B1: g_w1t [E][2816][2048] fp16, box {64,128}
    enc_f16(fn, &tB1, pw1, HDIM, 2 * IDIM, NEXP,
            (unsigned long long)HDIM * 2, (unsigned long long)HDIM * 2 * 2 * IDIM, 128);
    // A2: g_inter [16384, 1408] fp16, box {64,128}
    enc_f16(fn, &tA2, pint, IDIM, NSLOT, 1,
            (unsigned long long)IDIM * 2, (unsigned long long)IDIM * 2 * NSLOT, 128);
    // B2: g_w2t [E][2048][1408] fp16, box {64,128}
    enc_f16(fn, &tB2, pw2, IDIM, HDIM, NEXP,
            (unsigned long long)IDIM * 2, (unsigned long long)IDIM * 2 * HDIM, 128);

    cudaFuncSetAttribute(gemm1_tc, cudaFuncAttributeMaxDynamicSharedMemorySize, SMEM_DYN);
    cudaFuncSetAttribute(gemm2_tc, cudaFuncAttributeMaxDynamicSharedMemorySize, SMEM_DYN);

    route_kernel<<<1, 256>>>(ti);
    gather_x_kernel<<<NSLOT, 256>>>(x);
    transpose_w1_kernel<<<dim3(2 * IDIM / 32, HDIM / 32, NEXP), dim3(32, 8)>>>(gu);
    transpose_w2_kernel<<<dim3(HDIM / 32, IDIM / 32, NEXP), dim3(32, 8)>>>(dn);
    gemm1_tc<<<dim3(IDIM / 128, MAXT), 256, SMEM_DYN>>>(tA1, tB1);
    gemm2_tc<<<dim3(HDIM / 256, MAXT), 256, SMEM_DYN>>>(tA2, tB2);
    combine_kernel<<<(N_TOK * (HDIM / 4) + 255) / 256, 256>>>(tw, out);
}

// round 7
// speedup vs baseline: 7.7529x; 1.0156x over previous
#include <cuda_runtime.h>
#include <cuda.h>
#include <cuda_fp16.h>
#include <cstdint>

// ---------------- problem constants ----------------
#define N_TOK 8192
#define TOPK  2
#define NEXP  8
#define HDIM  2048
#define IDIM  1408
#define NSLOT (N_TOK * TOPK)           // 16384
#define BM    128
#define MAXT  (NSLOT / BM + NEXP)      // 136 worst-case M tiles

// ---------------- GEMM pipeline constants ----------------
#define KC      64                      // TMA box K width (128 bytes fp16)
#define KC2     128                     // K elements per pipeline stage (2 boxes)
#define STAGES  2
#define HBOX    (128 * KC * 2)          // 16384 bytes per 64-wide box
#define A_OFF   0                       // A: 2 boxes  (32 KB)
#define B0_OFF  (2 * HBOX)              // B half0: 2 boxes (32 KB)
#define B1_OFF  (4 * HBOX)              // B half1: 2 boxes (32 KB)
#define STAGE_B (6 * HBOX)              // 98304
#define SMEM_DYN (STAGES * STAGE_B + 1024)

// ---------------- scratch (static device globals) ----------------
__device__ __align__(16) __half g_ax   [(size_t)NSLOT * HDIM];            // sorted A, fp16
__device__ __align__(16) __half g_w1t  [(size_t)NEXP * 2 * IDIM * HDIM];  // [E][2816][2048]
__device__ __align__(16) __half g_w2t  [(size_t)NEXP * HDIM * IDIM];      // [E][2048][1408]
__device__ __align__(16) __half g_inter[(size_t)NSLOT * IDIM];            // fp16 SwiGLU out
__device__ __align__(16) float  g_outs [(size_t)NSLOT * HDIM];            // fp32 expert out
__device__ int g_pos2slot[NSLOT];
__device__ int g_slot2pos[NSLOT];
__device__ int g_tile_e[MAXT], g_tile_r0[MAXT], g_tile_rows[MAXT];
__device__ int g_ntiles;

// ---------------- PTX helpers ----------------
__device__ __forceinline__ uint32_t smem_u32(const void* p) {
    uint32_t a;
    asm("{ .reg .u64 t; cvta.to.shared.u64 t, %1; cvt.u32.u64 %0, t; }"
        : "=r"(a) : "l"(p));
    return a;
}
__device__ __forceinline__ void mbar_init(uint32_t a, uint32_t cnt) {
    asm volatile("mbarrier.init.shared.b64 [%0], %1;" :: "r"(a), "r"(cnt) : "memory");
}
__device__ __forceinline__ void mbar_expect(uint32_t a, uint32_t bytes) {
    asm volatile("mbarrier.arrive.expect_tx.shared.b64 _, [%0], %1;"
                 :: "r"(a), "r"(bytes) : "memory");
}
__device__ __forceinline__ void mbar_arrive(uint32_t a) {
    asm volatile("mbarrier.arrive.shared.b64 _, [%0];" :: "r"(a) : "memory");
}
__device__ __forceinline__ void mbar_wait(uint32_t a, uint32_t parity) {
    asm volatile(
        "{\n\t.reg .pred P;\n\t"
        "WL%=:\n\t"
        "mbarrier.try_wait.parity.acquire.cta.shared::cta.b64 P, [%0], %1, 0x989680;\n\t"
        "@P bra WD%=;\n\t"
        "bra WL%=;\n\t"
        "WD%=:\n\t}"
        :: "r"(a), "r"(parity) : "memory");
}
__device__ __forceinline__ void tma3d(uint32_t dst, const CUtensorMap* tm,
                                      int x, int y, int z, uint32_t mbar) {
    asm volatile(
        "cp.async.bulk.tensor.3d.shared::cta.global.tile.mbarrier::complete_tx::bytes "
        "[%0], [%1, {%2, %3, %4}], [%5];"
        :: "r"(dst), "l"(tm), "r"(x), "r"(y), "r"(z), "r"(mbar) : "memory");
}
__device__ __forceinline__ void ldsm4(uint32_t r[4], uint32_t addr) {
    asm volatile("ldmatrix.sync.aligned.m8n8.x4.shared.b16 {%0,%1,%2,%3}, [%4];"
                 : "=r"(r[0]), "=r"(r[1]), "=r"(r[2]), "=r"(r[3]) : "r"(addr));
}
__device__ __forceinline__ void mma16816(float c[4], const uint32_t a[4],
                                         uint32_t b0, uint32_t b1) {
    asm volatile(
        "mma.sync.aligned.m16n8k16.row.col.f32.f16.f16.f32 "
        "{%0,%1,%2,%3}, {%4,%5,%6,%7}, {%8,%9}, {%0,%1,%2,%3};"
        : "+f"(c[0]), "+f"(c[1]), "+f"(c[2]), "+f"(c[3])
        : "r"(a[0]), "r"(a[1]), "r"(a[2]), "r"(a[3]), "r"(b0), "r"(b1));
}
__device__ __forceinline__ uint32_t sw128(uint32_t off) {
    return off ^ ((off >> 3) & 0x70);
}

// ---------------- routing ----------------
__global__ void route_kernel(const int* __restrict__ topk_idx) {
    __shared__ int cnt[NEXP];
    __shared__ int cur[NEXP];
    int tid = threadIdx.x;
    if (tid < NEXP) cnt[tid] = 0;
    __syncthreads();
    for (int s = tid; s < NSLOT; s += blockDim.x)
        atomicAdd(&cnt[topk_idx[s]], 1);
    __syncthreads();
    if (tid == 0) {
        int off = 0, t = 0;
        for (int e = 0; e < NEXP; e++) {
            cur[e] = off;
            int c = cnt[e];
            for (int r = 0; r < c; r += BM) {
                g_tile_e[t] = e;
                g_tile_r0[t] = off + r;
                g_tile_rows[t] = (c - r < BM) ? (c - r) : BM;
                t++;
            }
            off += c;
        }
        g_ntiles = t;
    }
    __syncthreads();
    for (int s = tid; s < NSLOT; s += blockDim.x) {
        int p = atomicAdd(&cur[topk_idx[s]], 1);
        g_pos2slot[p] = s;
        g_slot2pos[s] = p;
    }
}

// ---------------- gather + fp16 convert of A ----------------
__global__ void gather_x_kernel(const float* __restrict__ x) {
    int pos = blockIdx.x;
    int token = g_pos2slot[pos] / TOPK;
    const float4* src = (const float4*)(x + (size_t)token * HDIM);
    uint2* dst = (uint2*)(g_ax + (size_t)pos * HDIM);
    for (int c = threadIdx.x; c < HDIM / 4; c += blockDim.x) {
        float4 v = src[c];
        __half2 a = __floats2half2_rn(v.x, v.y);
        __half2 b = __floats2half2_rn(v.z, v.w);
        uint2 u;
        u.x = *(uint32_t*)&a;
        u.y = *(uint32_t*)&b;
        dst[c] = u;
    }
}

// ---------------- weight transpose + fp16 convert ----------------
__global__ void transpose_w1_kernel(const float* __restrict__ w) {
    __shared__ float t[32][33];
    int e = blockIdx.z;
    int n0 = blockIdx.x * 32;   // 2I dim
    int k0 = blockIdx.y * 32;   // H dim
    int tx = threadIdx.x, ty = threadIdx.y;
    const float* src = w + (size_t)e * HDIM * (2 * IDIM);
#pragma unroll
    for (int i = 0; i < 32; i += 8)
        t[ty + i][tx] = src[(size_t)(k0 + ty + i) * (2 * IDIM) + n0 + tx];
    __syncthreads();
    __half* dst = g_w1t + (size_t)e * (2 * IDIM) * HDIM;
#pragma unroll
    for (int i = 0; i < 32; i += 8)
        dst[(size_t)(n0 + ty + i) * HDIM + k0 + tx] = __float2half(t[tx][ty + i]);
}
__global__ void transpose_w2_kernel(const float* __restrict__ w) {
    __shared__ float t[32][33];
    int e = blockIdx.z;
    int h0 = blockIdx.x * 32;   // H dim
    int i0 = blockIdx.y * 32;   // I dim
    int tx = threadIdx.x, ty = threadIdx.y;
    const float* src = w + (size_t)e * IDIM * HDIM;
#pragma unroll
    for (int i = 0; i < 32; i += 8)
        t[ty + i][tx] = src[(size_t)(i0 + ty + i) * HDIM + h0 + tx];
    __syncthreads();
    __half* dst = g_w2t + (size_t)e * HDIM * IDIM;
#pragma unroll
    for (int i = 0; i < 32; i += 8)
        dst[(size_t)(h0 + ty + i) * IDIM + i0 + tx] = __float2half(t[tx][ty + i]);
}

// ---------------- HMMA mainloop: M=128 x N=(128+128), TMA pipelined ---------
// KC2=128 per stage (two 64-wide boxes), 2 stages, register fragment
// double-buffering to break the ldmatrix->mma dependency chain.
// acc[mt][nt][frag]: mt = 16-row tile (4), nt 0-3 = half0 cols, 4-7 = half1.
__device__ __forceinline__ void hmma_mainloop(
    uint32_t sb, const CUtensorMap* tA, const CUtensorMap* tB,
    int row0, int y0, int y1, int ez, int nchunks, float acc[4][8][4])
{
    __shared__ __align__(8) unsigned long long mbar[2 * STAGES];
    int tid = threadIdx.x;
    uint32_t fb = smem_u32(&mbar[0]);
    uint32_t eb = smem_u32(&mbar[STAGES]);
    if (tid == 0) {
        for (int s = 0; s < STAGES; s++) {
            mbar_init(fb + 8u * s, 1);
            mbar_init(eb + 8u * s, 256);
        }
    }
    __syncthreads();
    if (tid == 0) {
        int npre = (STAGES < nchunks) ? STAGES : nchunks;
        for (int c = 0; c < npre; c++) {
            uint32_t st = sb + c * STAGE_B;
            mbar_expect(fb + 8u * c, STAGE_B);
#pragma unroll
            for (int h = 0; h < 2; h++) {
                int kx = c * KC2 + h * KC;
                tma3d(st + A_OFF  + h * HBOX, tA, kx, row0, 0,  fb + 8u * c);
                tma3d(st + B0_OFF + h * HBOX, tB, kx, y0,   ez, fb + 8u * c);
                tma3d(st + B1_OFF + h * HBOX, tB, kx, y1,   ez, fb + 8u * c);
            }
        }
    }
    int lane = tid & 31, warp = tid >> 5;
    int wm = warp >> 2, wn = warp & 3;               // 2m x 4n warp grid
    int aRow = wm * 64 + (lane & 15);                // + mt*16
    int aKb  = (lane >> 4) << 4;                     // + ksl*32
    int bRow = wn * 32 + (lane & 7) + ((lane >> 4) << 3);  // + pp*16
    int bKb  = ((lane >> 3) & 1) << 4;               // + ksl*32

    uint32_t afr[2][4][4];   // [buf][mt][reg]
    uint32_t bfr[2][4][4];   // [buf][half*2+pp][reg]

    for (int c = 0; c < nchunks; c++) {
        int s = c & 1;
        uint32_t st = sb + s * STAGE_B;
        mbar_wait(fb + 8u * s, (c >> 1) & 1);

        // prime ks = 0 into buffer 0
        {
            uint32_t aB  = st + A_OFF;
            uint32_t b0B = st + B0_OFF;
            uint32_t b1B = st + B1_OFF;
#pragma unroll
            for (int mt = 0; mt < 4; mt++)
                ldsm4(afr[0][mt], aB + sw128((uint32_t)(aRow + mt * 16) * 128 + aKb));
#pragma unroll
            for (int hp = 0; hp < 4; hp++) {
                uint32_t base = (hp >> 1) ? b1B : b0B;
                int pp = hp & 1;
                ldsm4(bfr[0][hp], base + sw128((uint32_t)(bRow + pp * 16) * 128 + bKb));
            }
        }
#pragma unroll
        for (int ks = 0; ks < KC2 / 16; ks++) {
            int cur = ks & 1;
            if (ks < KC2 / 16 - 1) {
                int kn = ks + 1;
                int h = kn >> 2, ksl = kn & 3;
                uint32_t aB  = st + A_OFF  + h * HBOX;
                uint32_t b0B = st + B0_OFF + h * HBOX;
                uint32_t b1B = st + B1_OFF + h * HBOX;
#pragma unroll
                for (int mt = 0; mt < 4; mt++)
                    ldsm4(afr[cur ^ 1][mt],
                          aB + sw128((uint32_t)(aRow + mt * 16) * 128 + aKb + ksl * 32));
#pragma unroll
                for (int hp = 0; hp < 4; hp++) {
                    uint32_t base = (hp >> 1) ? b1B : b0B;
                    int pp = hp & 1;
                    ldsm4(bfr[cur ^ 1][hp],
                          base + sw128((uint32_t)(bRow + pp * 16) * 128 + bKb + ksl * 32));
                }
            }
#pragma unroll
            for (int hp = 0; hp < 4; hp++) {
                int nt = (hp >> 1) * 4 + (hp & 1) * 2;
#pragma unroll
                for (int mt = 0; mt < 4; mt++) {
                    mma16816(acc[mt][nt],     afr[cur][mt], bfr[cur][hp][0], bfr[cur][hp][1]);
                    mma16816(acc[mt][nt + 1], afr[cur][mt], bfr[cur][hp][2], bfr[cur][hp][3]);
                }
            }
        }
        mbar_arrive(eb + 8u * s);
        if (tid == 0 && c + STAGES < nchunks) {
            mbar_wait(eb + 8u * s, (c >> 1) & 1);
            int cn = c + STAGES;
            mbar_expect(fb + 8u * s, STAGE_B);
#pragma unroll
            for (int h = 0; h < 2; h++) {
                int kx = cn * KC2 + h * KC;
                tma3d(st + A_OFF  + h * HBOX, tA, kx, row0, 0,  fb + 8u * s);
                tma3d(st + B0_OFF + h * HBOX, tB, kx, y0,   ez, fb + 8u * s);
                tma3d(st + B1_OFF + h * HBOX, tB, kx, y1,   ez, fb + 8u * s);
            }
        }
    }
}

// ---------------- GEMM1: A_sorted @ w1t (gate+up) + fused SwiGLU ------------
// N tile: 128 gate cols (c0..) paired with 128 up cols (IDIM+c0..)
__global__ __launch_bounds__(256, 1) void gemm1_tc(
    const __grid_constant__ CUtensorMap tA,
    const __grid_constant__ CUtensorMap tB)
{
    int t = blockIdx.y;
    if (t >= g_ntiles) return;
    int e = g_tile_e[t], row0 = g_tile_r0[t], rows = g_tile_rows[t];
    int c0 = blockIdx.x * 128;
    extern __shared__ __align__(1024) char dsm[];
    uint32_t sb = (smem_u32(dsm) + 1023u) & ~1023u;

    float acc[4][8][4];
#pragma unroll
    for (int i = 0; i < 4; i++)
#pragma unroll
        for (int j = 0; j < 8; j++)
#pragma unroll
            for (int q = 0; q < 4; q++) acc[i][j][q] = 0.f;

    hmma_mainloop(sb, &tA, &tB, row0, c0, IDIM + c0, e, HDIM / KC2, acc);

    int lane = threadIdx.x & 31, warp = threadIdx.x >> 5;
    int wm = warp >> 2, wn = warp & 3;
#pragma unroll
    for (int mt = 0; mt < 4; mt++) {
#pragma unroll
        for (int nt = 0; nt < 4; nt++) {
            int col = c0 + wn * 32 + nt * 8 + 2 * (lane & 3);
            int r_lo = wm * 64 + mt * 16 + (lane >> 2);
            float g0 = acc[mt][nt][0], g1 = acc[mt][nt][1];
            float u0 = acc[mt][nt + 4][0], u1 = acc[mt][nt + 4][1];
            if (r_lo < rows) {
                float o0 = u0 * (g0 / (1.f + __expf(-g0)));
                float o1 = u1 * (g1 / (1.f + __expf(-g1)));
                __half2 p = __floats2half2_rn(o0, o1);
                *(__half2*)(g_inter + (size_t)(row0 + r_lo) * IDIM + col) = p;
            }
            int r_hi = r_lo + 8;
            g0 = acc[mt][nt][2]; g1 = acc[mt][nt][3];
            u0 = acc[mt][nt + 4][2]; u1 = acc[mt][nt + 4][3];
            if (r_hi < rows) {
                float o0 = u0 * (g0 / (1.f + __expf(-g0)));
                float o1 = u1 * (g1 / (1.f + __expf(-g1)));
                __half2 p = __floats2half2_rn(o0, o1);
                *(__half2*)(g_inter + (size_t)(row0 + r_hi) * IDIM + col) = p;
            }
        }
    }
}

// ---------------- GEMM2: g_inter @ w2t -> g_outs ----------------------------
__global__ __launch_bounds__(256, 1) void gemm2_tc(
    const __grid_constant__ CUtensorMap tA,
    const __grid_constant__ CUtensorMap tB)
{
    int t = blockIdx.y;
    if (t >= g_ntiles) return;
    int e = g_tile_e[t], row0 = g_tile_r0[t], rows = g_tile_rows[t];
    int n0 = blockIdx.x * 256;
    extern __shared__ __align__(1024) char dsm[];
    uint32_t sb = (smem_u32(dsm) + 1023u) & ~1023u;

    float acc[4][8][4];
#pragma unroll
    for (int i = 0; i < 4; i++)
#pragma unroll
        for (int j = 0; j < 8; j++)
#pragma unroll
            for (int q = 0; q < 4; q++) acc[i][j][q] = 0.f;

    hmma_mainloop(sb, &tA, &tB, row0, n0, n0 + 128, e, IDIM / KC2, acc);

    int lane = threadIdx.x & 31, warp = threadIdx.x >> 5;
    int wm = warp >> 2, wn = warp & 3;
#pragma unroll
    for (int mt = 0; mt < 4; mt++) {
#pragma unroll
        for (int nt = 0; nt < 8; nt++) {
            int colh = (nt < 4) ? (wn * 32 + nt * 8) : (128 + wn * 32 + (nt - 4) * 8);
            int col = n0 + colh + 2 * (lane & 3);
            int r_lo = wm * 64 + mt * 16 + (lane >> 2);
            if (r_lo < rows) {
                float2 v = make_float2(acc[mt][nt][0], acc[mt][nt][1]);
                *(float2*)(g_outs + (size_t)(row0 + r_lo) * HDIM + col) = v;
            }
            int r_hi = r_lo + 8;
            if (r_hi < rows) {
                float2 v = make_float2(acc[mt][nt][2], acc[mt][nt][3]);
                *(float2*)(g_outs + (size_t)(row0 + r_hi) * HDIM + col) = v;
            }
        }
    }
}

// ---------------- combine: weighted unroute ----------------
__global__ void combine_kernel(const float* __restrict__ tw,
                               float* __restrict__ out) {
    const int HQ = HDIM / 4;
    int idx = blockIdx.x * blockDim.x + threadIdx.x;
    if (idx >= N_TOK * HQ) return;
    int n = idx / HQ;
    int hq = idx - n * HQ;
    int p0 = g_slot2pos[n * TOPK + 0];
    int p1 = g_slot2pos[n * TOPK + 1];
    float w0 = tw[n * TOPK + 0];
    float w1 = tw[n * TOPK + 1];
    const float4* o4 = (const float4*)g_outs;
    float4 v0 = o4[(size_t)p0 * HQ + hq];
    float4 v1 = o4[(size_t)p1 * HQ + hq];
    float4 r;
    r.x = w0 * v0.x + w1 * v1.x;
    r.y = w0 * v0.y + w1 * v1.y;
    r.z = w0 * v0.z + w1 * v1.z;
    r.w = w0 * v0.w + w1 * v1.w;
    ((float4*)out)[idx] = r;
}

// ---------------- host ----------------
typedef CUresult (*encfn_t)(CUtensorMap*, CUtensorMapDataType, cuuint32_t, void*,
                            const cuuint64_t*, const cuuint64_t*, const cuuint32_t*,
                            const cuuint32_t*, CUtensorMapInterleave, CUtensorMapSwizzle,
                            CUtensorMapL2promotion, CUtensorMapFloatOOBfill);

static void enc_f16(encfn_t fn, CUtensorMap* m, void* p,
                    unsigned long long d0, unsigned long long d1, unsigned long long d2,
                    unsigned long long s1, unsigned long long s2, unsigned box1) {
    cuuint64_t dims[3] = {d0, d1, d2};
    cuuint64_t str[2]  = {s1, s2};
    cuuint32_t box[3]  = {KC, box1, 1};
    cuuint32_t es[3]   = {1, 1, 1};
    fn(m, CU_TENSOR_MAP_DATA_TYPE_FLOAT16, 3, p, dims, str, box, es,
       CU_TENSOR_MAP_INTERLEAVE_NONE, CU_TENSOR_MAP_SWIZZLE_128B,
       CU_TENSOR_MAP_L2_PROMOTION_L2_128B, CU_TENSOR_MAP_FLOAT_OOB_FILL_NONE);
}

extern "C" void kernel_launch(void* const* d_in, const int* in_sizes, int n_in,
                              void* d_out, int out_size) {
    const float* x  = (const float*)d_in[0];
    const int*   ti = (const int*)  d_in[1];
    const float* tw = (const float*)d_in[2];
    const float* gu = (const float*)d_in[3];
    const float* dn = (const float*)d_in[4];
    float* out = (float*)d_out;

    void* fp = nullptr;
    cudaDriverEntryPointQueryResult qr;
    cudaGetDriverEntryPointByVersion("cuTensorMapEncodeTiled", &fp, 12000,
                                     cudaEnableDefault, &qr);
    encfn_t fn = (encfn_t)fp;

    void *pax, *pw1, *pw2, *pint;
    cudaGetSymbolAddress(&pax,  g_ax);
    cudaGetSymbolAddress(&pw1,  g_w1t);
    cudaGetSymbolAddress(&pw2,  g_w2t);
    cudaGetSymbolAddress(&pint, g_inter);

    CUtensorMap tA1, tB1, tA2, tB2;
    // A1: g_ax [16384, 2048] fp16, box {64,128}
    enc_f16(fn, &tA1, pax, HDIM, NSLOT, 1,
            (unsigned long long)HDIM * 2, (unsigned long long)HDIM * 2 * NSLOT, 128);
    // B1: g_w1t [E][2816][2048] fp16, box {64,128}
    enc_f16(fn, &tB1, pw1, HDIM, 2 * IDIM, NEXP,
            (unsigned long long)HDIM * 2, (unsigned long long)HDIM * 2 * 2 * IDIM, 128);
    // A2: g_inter [16384, 1408] fp16, box {64,128}
    enc_f16(fn, &tA2, pint, IDIM, NSLOT, 1,
            (unsigned long long)IDIM * 2, (unsigned long long)IDIM * 2 * NSLOT, 128);
    // B2: g_w2t [E][2048][1408] fp16, box {64,128}
    enc_f16(fn, &tB2, pw2, IDIM, HDIM, NEXP,
            (unsigned long long)IDIM * 2, (unsigned long long)IDIM * 2 * HDIM, 128);

    cudaFuncSetAttribute(gemm1_tc, cudaFuncAttributeMaxDynamicSharedMemorySize, SMEM_DYN);
    cudaFuncSetAttribute(gemm2_tc, cudaFuncAttributeMaxDynamicSharedMemorySize, SMEM_DYN);

    route_kernel<<<1, 256>>>(ti);
    gather_x_kernel<<<NSLOT, 256>>>(x);
    transpose_w1_kernel<<<dim3(2 * IDIM / 32, HDIM / 32, NEXP), dim3(32, 8)>>>(gu);
    transpose_w2_kernel<<<dim3(HDIM / 32, IDIM / 32, NEXP), dim3(32, 8)>>>(dn);
    gemm1_tc<<<dim3(IDIM / 128, MAXT), 256, SMEM_DYN>>>(tA1, tB1);
    gemm2_tc<<<dim3(HDIM / 256, MAXT), 256, SMEM_DYN>>>(tA2, tB2);
    combine_kernel<<<(N_TOK * (HDIM / 4) + 255) / 256, 256>>>(tw, out);
}

// round 9
// speedup vs baseline: 7.9868x; 1.0302x over previous
#include <cuda_runtime.h>
#include <cuda.h>
#include <cuda_fp16.h>
#include <cstdint>

// ---------------- problem constants ----------------
#define N_TOK 8192
#define TOPK  2
#define NEXP  8
#define HDIM  2048
#define IDIM  1408
#define NSLOT (N_TOK * TOPK)           // 16384
#define BM    128
#define MAXT  (NSLOT / BM + NEXP)      // 136 worst-case M tiles

// ---------------- GEMM pipeline constants ----------------
#define KC      64                      // K elements per chunk (128 bytes fp16)
#define STAGES  3
#define A_BYTES (128 * KC * 2)          // 16384: A tile 128 rows
#define B_BYTES (128 * KC * 2)          // 16384: B tile 128 rows (2 halves of 64)
#define STAGE_B (A_BYTES + B_BYTES)     // 32768
#define SMEM_DYN (STAGES * STAGE_B + 1024)   // ~99 KB -> 2 CTAs/SM

// ---------------- scratch (static device globals) ----------------
__device__ __align__(16) __half g_ax   [(size_t)NSLOT * HDIM];            // sorted A, fp16
__device__ __align__(16) __half g_w1t  [(size_t)NEXP * 2 * IDIM * HDIM];  // [E][2816][2048]
__device__ __align__(16) __half g_w2t  [(size_t)NEXP * HDIM * IDIM];      // [E][2048][1408]
__device__ __align__(16) __half g_inter[(size_t)NSLOT * IDIM];            // fp16 SwiGLU out
__device__ __align__(16) float  g_outs [(size_t)NSLOT * HDIM];            // fp32 expert out
__device__ int g_pos2slot[NSLOT];
__device__ int g_slot2pos[NSLOT];
__device__ int g_tile_e[MAXT], g_tile_r0[MAXT], g_tile_rows[MAXT];
__device__ int g_ntiles;

// ---------------- PTX helpers ----------------
__device__ __forceinline__ uint32_t smem_u32(const void* p) {
    uint32_t a;
    asm("{ .reg .u64 t; cvta.to.shared.u64 t, %1; cvt.u32.u64 %0, t; }"
        : "=r"(a) : "l"(p));
    return a;
}
__device__ __forceinline__ void mbar_init(uint32_t a, uint32_t cnt) {
    asm volatile("mbarrier.init.shared.b64 [%0], %1;" :: "r"(a), "r"(cnt) : "memory");
}
__device__ __forceinline__ void mbar_expect(uint32_t a, uint32_t bytes) {
    asm volatile("mbarrier.arrive.expect_tx.shared.b64 _, [%0], %1;"
                 :: "r"(a), "r"(bytes) : "memory");
}
__device__ __forceinline__ void mbar_arrive(uint32_t a) {
    asm volatile("mbarrier.arrive.shared.b64 _, [%0];" :: "r"(a) : "memory");
}
__device__ __forceinline__ void mbar_wait(uint32_t a, uint32_t parity) {
    asm volatile(
        "{\n\t.reg .pred P;\n\t"
        "WL%=:\n\t"
        "mbarrier.try_wait.parity.acquire.cta.shared::cta.b64 P, [%0], %1, 0x989680;\n\t"
        "@P bra WD%=;\n\t"
        "bra WL%=;\n\t"
        "WD%=:\n\t}"
        :: "r"(a), "r"(parity) : "memory");
}
__device__ __forceinline__ void tma3d(uint32_t dst, const CUtensorMap* tm,
                                      int x, int y, int z, uint32_t mbar) {
    asm volatile(
        "cp.async.bulk.tensor.3d.shared::cta.global.tile.mbarrier::complete_tx::bytes "
        "[%0], [%1, {%2, %3, %4}], [%5];"
        :: "r"(dst), "l"(tm), "r"(x), "r"(y), "r"(z), "r"(mbar) : "memory");
}
__device__ __forceinline__ void ldsm4(uint32_t r[4], uint32_t addr) {
    asm volatile("ldmatrix.sync.aligned.m8n8.x4.shared.b16 {%0,%1,%2,%3}, [%4];"
                 : "=r"(r[0]), "=r"(r[1]), "=r"(r[2]), "=r"(r[3]) : "r"(addr));
}
__device__ __forceinline__ void mma16816(float c[4], const uint32_t a[4],
                                         uint32_t b0, uint32_t b1) {
    asm volatile(
        "mma.sync.aligned.m16n8k16.row.col.f32.f16.f16.f32 "
        "{%0,%1,%2,%3}, {%4,%5,%6,%7}, {%8,%9}, {%0,%1,%2,%3};"
        : "+f"(c[0]), "+f"(c[1]), "+f"(c[2]), "+f"(c[3])
        : "r"(a[0]), "r"(a[1]), "r"(a[2]), "r"(a[3]), "r"(b0), "r"(b1));
}
__device__ __forceinline__ uint32_t sw128(uint32_t off) {
    return off ^ ((off >> 3) & 0x70);
}

// ---------------- routing ----------------
__global__ void route_kernel(const int* __restrict__ topk_idx) {
    __shared__ int cnt[NEXP];
    __shared__ int cur[NEXP];
    int tid = threadIdx.x;
    if (tid < NEXP) cnt[tid] = 0;
    __syncthreads();
    for (int s = tid; s < NSLOT; s += blockDim.x)
        atomicAdd(&cnt[topk_idx[s]], 1);
    __syncthreads();
    if (tid == 0) {
        int off = 0, t = 0;
        for (int e = 0; e < NEXP; e++) {
            cur[e] = off;
            int c = cnt[e];
            for (int r = 0; r < c; r += BM) {
                g_tile_e[t] = e;
                g_tile_r0[t] = off + r;
                g_tile_rows[t] = (c - r < BM) ? (c - r) : BM;
                t++;
            }
            off += c;
        }
        g_ntiles = t;
    }
    __syncthreads();
    for (int s = tid; s < NSLOT; s += blockDim.x) {
        int p = atomicAdd(&cur[topk_idx[s]], 1);
        g_pos2slot[p] = s;
        g_slot2pos[s] = p;
    }
}

// ---------------- gather + fp16 convert of A ----------------
__global__ void gather_x_kernel(const float* __restrict__ x) {
    int pos = blockIdx.x;
    int token = g_pos2slot[pos] / TOPK;
    const float4* src = (const float4*)(x + (size_t)token * HDIM);
    uint2* dst = (uint2*)(g_ax + (size_t)pos * HDIM);
    for (int c = threadIdx.x; c < HDIM / 4; c += blockDim.x) {
        float4 v = src[c];
        __half2 a = __floats2half2_rn(v.x, v.y);
        __half2 b = __floats2half2_rn(v.z, v.w);
        uint2 u;
        u.x = *(uint32_t*)&a;
        u.y = *(uint32_t*)&b;
        dst[c] = u;
    }
}

// ---------------- weight transpose + fp16 convert ----------------
__global__ void transpose_w1_kernel(const float* __restrict__ w) {
    __shared__ float t[32][33];
    int e = blockIdx.z;
    int n0 = blockIdx.x * 32;   // 2I dim
    int k0 = blockIdx.y * 32;   // H dim
    int tx = threadIdx.x, ty = threadIdx.y;
    const float* src = w + (size_t)e * HDIM * (2 * IDIM);
#pragma unroll
    for (int i = 0; i < 32; i += 8)
        t[ty + i][tx] = src[(size_t)(k0 + ty + i) * (2 * IDIM) + n0 + tx];
    __syncthreads();
    __half* dst = g_w1t + (size_t)e * (2 * IDIM) * HDIM;
#pragma unroll
    for (int i = 0; i < 32; i += 8)
        dst[(size_t)(n0 + ty + i) * HDIM + k0 + tx] = __float2half(t[tx][ty + i]);
}
__global__ void transpose_w2_kernel(const float* __restrict__ w) {
    __shared__ float t[32][33];
    int e = blockIdx.z;
    int h0 = blockIdx.x * 32;   // H dim
    int i0 = blockIdx.y * 32;   // I dim
    int tx = threadIdx.x, ty = threadIdx.y;
    const float* src = w + (size_t)e * IDIM * HDIM;
#pragma unroll
    for (int i = 0; i < 32; i += 8)
        t[ty + i][tx] = src[(size_t)(i0 + ty + i) * HDIM + h0 + tx];
    __syncthreads();
    __half* dst = g_w2t + (size_t)e * HDIM * IDIM;
#pragma unroll
    for (int i = 0; i < 32; i += 8)
        dst[(size_t)(h0 + ty + i) * IDIM + i0 + tx] = __float2half(t[tx][ty + i]);
}

// ---------------- HMMA mainloop: M=128 x N=(64+64), 3-stage, 2 CTAs/SM ------
// B tile per stage: rows 0..63 from y0 (half0), rows 64..127 from y1 (half1).
// Warp grid 4m x 2n; warp tile 32M x (32+32)N.
// acc[mt][nt][frag]: mt = 16-row tile (2), nt 0-3 = half0 cols, 4-7 = half1.
__device__ __forceinline__ void hmma_mainloop(
    uint32_t sb, const CUtensorMap* tA, const CUtensorMap* tB,
    int row0, int y0, int y1, int ez, int nchunks, float acc[2][8][4])
{
    __shared__ __align__(8) unsigned long long mbar[2 * STAGES];
    int tid = threadIdx.x;
    uint32_t fb = smem_u32(&mbar[0]);
    uint32_t eb = smem_u32(&mbar[STAGES]);
    if (tid == 0) {
        for (int s = 0; s < STAGES; s++) {
            mbar_init(fb + 8u * s, 1);
            mbar_init(eb + 8u * s, 256);
        }
    }
    __syncthreads();
    if (tid == 0) {
        int npre = (STAGES < nchunks) ? STAGES : nchunks;
        for (int c = 0; c < npre; c++) {
            uint32_t st = sb + c * STAGE_B;
            mbar_expect(fb + 8u * c, STAGE_B);
            tma3d(st,                          tA, c * KC, row0, 0,  fb + 8u * c);
            tma3d(st + A_BYTES,                tB, c * KC, y0,   ez, fb + 8u * c);
            tma3d(st + A_BYTES + B_BYTES / 2,  tB, c * KC, y1,   ez, fb + 8u * c);
        }
    }
    int lane = tid & 31, warp = tid >> 5;
    int wm = warp >> 1, wn = warp & 1;               // 4m x 2n warp grid
    int aRow = wm * 32 + (lane & 15);                // + mt*16
    int aKb  = (lane >> 4) << 4;                     // + ks*32
    int bRow = wn * 32 + (lane & 7) + ((lane >> 4) << 3);  // + pp*16 (+64 for half1)
    int bKb  = ((lane >> 3) & 1) << 4;               // + ks*32

    int s = 0, parity = 0;
    for (int c = 0; c < nchunks; c++) {
        uint32_t st = sb + s * STAGE_B;
        mbar_wait(fb + 8u * s, parity);
        uint32_t aB = st, bB = st + A_BYTES;
#pragma unroll
        for (int ks = 0; ks < KC / 16; ks++) {
            uint32_t a[2][4];
#pragma unroll
            for (int mt = 0; mt < 2; mt++) {
                uint32_t off = (uint32_t)(aRow + mt * 16) * 128 + aKb + ks * 32;
                ldsm4(a[mt], aB + sw128(off));
            }
#pragma unroll
            for (int half = 0; half < 2; half++) {
#pragma unroll
                for (int pp = 0; pp < 2; pp++) {
                    uint32_t off = (uint32_t)(half * 64 + bRow + pp * 16) * 128
                                   + bKb + ks * 32;
                    uint32_t b[4];
                    ldsm4(b, bB + sw128(off));
                    int nt = half * 4 + pp * 2;
                    mma16816(acc[0][nt],     a[0], b[0], b[1]);
                    mma16816(acc[0][nt + 1], a[0], b[2], b[3]);
                    mma16816(acc[1][nt],     a[1], b[0], b[1]);
                    mma16816(acc[1][nt + 1], a[1], b[2], b[3]);
                }
            }
        }
        mbar_arrive(eb + 8u * s);
        if (tid == 0 && c + STAGES < nchunks) {
            mbar_wait(eb + 8u * s, parity);
            int cn = c + STAGES;
            mbar_expect(fb + 8u * s, STAGE_B);
            tma3d(st,                         tA, cn * KC, row0, 0,  fb + 8u * s);
            tma3d(st + A_BYTES,               tB, cn * KC, y0,   ez, fb + 8u * s);
            tma3d(st + A_BYTES + B_BYTES / 2, tB, cn * KC, y1,   ez, fb + 8u * s);
        }
        if (++s == STAGES) { s = 0; parity ^= 1; }
    }
}

// ---------------- GEMM1: A_sorted @ w1t (gate+up) + fused SwiGLU ------------
// N tile: 64 gate cols (c0..) paired with 64 up cols (IDIM+c0..)
__global__ __launch_bounds__(256, 2) void gemm1_tc(
    const __grid_constant__ CUtensorMap tA,
    const __grid_constant__ CUtensorMap tB)
{
    int t = blockIdx.y;
    if (t >= g_ntiles) return;
    int e = g_tile_e[t], row0 = g_tile_r0[t], rows = g_tile_rows[t];
    int c0 = blockIdx.x * 64;
    extern __shared__ __align__(1024) char dsm[];
    uint32_t sb = (smem_u32(dsm) + 1023u) & ~1023u;

    float acc[2][8][4];
#pragma unroll
    for (int i = 0; i < 2; i++)
#pragma unroll
        for (int j = 0; j < 8; j++)
#pragma unroll
            for (int q = 0; q < 4; q++) acc[i][j][q] = 0.f;

    hmma_mainloop(sb, &tA, &tB, row0, c0, IDIM + c0, e, HDIM / KC, acc);

    int lane = threadIdx.x & 31, warp = threadIdx.x >> 5;
    int wm = warp >> 1, wn = warp & 1;
#pragma unroll
    for (int mt = 0; mt < 2; mt++) {
#pragma unroll
        for (int nt = 0; nt < 4; nt++) {
            int col = c0 + wn * 32 + nt * 8 + 2 * (lane & 3);
            int r_lo = wm * 32 + mt * 16 + (lane >> 2);
            float g0 = acc[mt][nt][0], g1 = acc[mt][nt][1];
            float u0 = acc[mt][nt + 4][0], u1 = acc[mt][nt + 4][1];
            if (r_lo < rows) {
                float o0 = u0 * (g0 / (1.f + __expf(-g0)));
                float o1 = u1 * (g1 / (1.f + __expf(-g1)));
                __half2 p = __floats2half2_rn(o0, o1);
                *(__half2*)(g_inter + (size_t)(row0 + r_lo) * IDIM + col) = p;
            }
            int r_hi = r_lo + 8;
            g0 = acc[mt][nt][2]; g1 = acc[mt][nt][3];
            u0 = acc[mt][nt + 4][2]; u1 = acc[mt][nt + 4][3];
            if (r_hi < rows) {
                float o0 = u0 * (g0 / (1.f + __expf(-g0)));
                float o1 = u1 * (g1 / (1.f + __expf(-g1)));
                __half2 p = __floats2half2_rn(o0, o1);
                *(__half2*)(g_inter + (size_t)(row0 + r_hi) * IDIM + col) = p;
            }
        }
    }
}

// ---------------- GEMM2: g_inter @ w2t -> g_outs ----------------------------
__global__ __launch_bounds__(256, 2) void gemm2_tc(
    const __grid_constant__ CUtensorMap tA,
    const __grid_constant__ CUtensorMap tB)
{
    int t = blockIdx.y;
    if (t >= g_ntiles) return;
    int e = g_tile_e[t], row0 = g_tile_r0[t], rows = g_tile_rows[t];
    int n0 = blockIdx.x * 128;
    extern __shared__ __align__(1024) char dsm[];
    uint32_t sb = (smem_u32(dsm) + 1023u) & ~1023u;

    float acc[2][8][4];
#pragma unroll
    for (int i = 0; i < 2; i++)
#pragma unroll
        for (int j = 0; j < 8; j++)
#pragma unroll
            for (int q = 0; q < 4; q++) acc[i][j][q] = 0.f;

    hmma_mainloop(sb, &tA, &tB, row0, n0, n0 + 64, e, IDIM / KC, acc);

    int lane = threadIdx.x & 31, warp = threadIdx.x >> 5;
    int wm = warp >> 1, wn = warp & 1;
#pragma unroll
    for (int mt = 0; mt < 2; mt++) {
#pragma unroll
        for (int nt = 0; nt < 8; nt++) {
            int colh = (nt < 4) ? (wn * 32 + nt * 8) : (64 + wn * 32 + (nt - 4) * 8);
            int col = n0 + colh + 2 * (lane & 3);
            int r_lo = wm * 32 + mt * 16 + (lane >> 2);
            if (r_lo < rows) {
                float2 v = make_float2(acc[mt][nt][0], acc[mt][nt][1]);
                *(float2*)(g_outs + (size_t)(row0 + r_lo) * HDIM + col) = v;
            }
            int r_hi = r_lo + 8;
            if (r_hi < rows) {
                float2 v = make_float2(acc[mt][nt][2], acc[mt][nt][3]);
                *(float2*)(g_outs + (size_t)(row0 + r_hi) * HDIM + col) = v;
            }
        }
    }
}

// ---------------- combine: weighted unroute ----------------
__global__ void combine_kernel(const float* __restrict__ tw,
                               float* __restrict__ out) {
    const int HQ = HDIM / 4;
    int idx = blockIdx.x * blockDim.x + threadIdx.x;
    if (idx >= N_TOK * HQ) return;
    int n = idx / HQ;
    int hq = idx - n * HQ;
    int p0 = g_slot2pos[n * TOPK + 0];
    int p1 = g_slot2pos[n * TOPK + 1];
    float w0 = tw[n * TOPK + 0];
    float w1 = tw[n * TOPK + 1];
    const float4* o4 = (const float4*)g_outs;
    float4 v0 = o4[(size_t)p0 * HQ + hq];
    float4 v1 = o4[(size_t)p1 * HQ + hq];
    float4 r;
    r.x = w0 * v0.x + w1 * v1.x;
    r.y = w0 * v0.y + w1 * v1.y;
    r.z = w0 * v0.z + w1 * v1.z;
    r.w = w0 * v0.w + w1 * v1.w;
    ((float4*)out)[idx] = r;
}

// ---------------- host ----------------
typedef CUresult (*encfn_t)(CUtensorMap*, CUtensorMapDataType, cuuint32_t, void*,
                            const cuuint64_t*, const cuuint64_t*, const cuuint32_t*,
                            const cuuint32_t*, CUtensorMapInterleave, CUtensorMapSwizzle,
                            CUtensorMapL2promotion, CUtensorMapFloatOOBfill);

static void enc_f16(encfn_t fn, CUtensorMap* m, void* p,
                    unsigned long long d0, unsigned long long d1, unsigned long long d2,
                    unsigned long long s1, unsigned long long s2, unsigned box1) {
    cuuint64_t dims[3] = {d0, d1, d2};
    cuuint64_t str[2]  = {s1, s2};
    cuuint32_t box[3]  = {KC, box1, 1};
    cuuint32_t es[3]   = {1, 1, 1};
    fn(m, CU_TENSOR_MAP_DATA_TYPE_FLOAT16, 3, p, dims, str, box, es,
       CU_TENSOR_MAP_INTERLEAVE_NONE, CU_TENSOR_MAP_SWIZZLE_128B,
       CU_TENSOR_MAP_L2_PROMOTION_L2_128B, CU_TENSOR_MAP_FLOAT_OOB_FILL_NONE);
}

extern "C" void kernel_launch(void* const* d_in, const int* in_sizes, int n_in,
                              void* d_out, int out_size) {
    const float* x  = (const float*)d_in[0];
    const int*   ti = (const int*)  d_in[1];
    const float* tw = (const float*)d_in[2];
    const float* gu = (const float*)d_in[3];
    const float* dn = (const float*)d_in[4];
    float* out = (float*)d_out;

    void* fp = nullptr;
    cudaDriverEntryPointQueryResult qr;
    cudaGetDriverEntryPointByVersion("cuTensorMapEncodeTiled", &fp, 12000,
                                     cudaEnableDefault, &qr);
    encfn_t fn = (encfn_t)fp;

    void *pax, *pw1, *pw2, *pint;
    cudaGetSymbolAddress(&pax,  g_ax);
    cudaGetSymbolAddress(&pw1,  g_w1t);
    cudaGetSymbolAddress(&pw2,  g_w2t);
    cudaGetSymbolAddress(&pint, g_inter);

    CUtensorMap tA1, tB1, tA2, tB2;
    // A1: g_ax [16384, 2048] fp16, box {64,128}
    enc_f16(fn, &tA1, pax, HDIM, NSLOT, 1,
            (unsigned long long)HDIM * 2, (unsigned long long)HDIM * 2 * NSLOT, 128);
    // B1: g_w1t [E][2816][2048] fp16, box {64,64}
    enc_f16(fn, &tB1, pw1, HDIM, 2 * IDIM, NEXP,
            (unsigned long long)HDIM * 2, (unsigned long long)HDIM * 2 * 2 * IDIM, 64);
    // A2: g_inter [16384, 1408] fp16, box {64,128}
    enc_f16(fn, &tA2, pint, IDIM, NSLOT, 1,
            (unsigned long long)IDIM * 2, (unsigned long long)IDIM * 2 * NSLOT, 128);
    // B2: g_w2t [E][2048][1408] fp16, box {64,64}
    enc_f16(fn, &tB2, pw2, IDIM, HDIM, NEXP,
            (unsigned long long)IDIM * 2, (unsigned long long)IDIM * 2 * HDIM, 64);

    cudaFuncSetAttribute(gemm1_tc, cudaFuncAttributeMaxDynamicSharedMemorySize, SMEM_DYN);
    cudaFuncSetAttribute(gemm2_tc, cudaFuncAttributeMaxDynamicSharedMemorySize, SMEM_DYN);

    route_kernel<<<1, 256>>>(ti);
    gather_x_kernel<<<NSLOT, 256>>>(x);
    transpose_w1_kernel<<<dim3(2 * IDIM / 32, HDIM / 32, NEXP), dim3(32, 8)>>>(gu);
    transpose_w2_kernel<<<dim3(HDIM / 32, IDIM / 32, NEXP), dim3(32, 8)>>>(dn);
    gemm1_tc<<<dim3(IDIM / 64, MAXT), 256, SMEM_DYN>>>(tA1, tB1);
    gemm2_tc<<<dim3(HDIM / 128, MAXT), 256, SMEM_DYN>>>(tA2, tB2);
    combine_kernel<<<(N_TOK * (HDIM / 4) + 255) / 256, 256>>>(tw, out);
}

// round 14
// speedup vs baseline: 8.2566x; 1.0338x over previous
#include <cuda_runtime.h>
#include <cuda.h>
#include <cuda_fp16.h>
#include <cstdint>

// ---------------- problem constants ----------------
#define N_TOK 8192
#define TOPK  2
#define NEXP  8
#define HDIM  2048
#define IDIM  1408
#define NSLOT (N_TOK * TOPK)           // 16384
#define BM    128
#define MAXT  (NSLOT / BM + NEXP)      // 136 worst-case M tiles

// ---------------- GEMM pipeline constants ----------------
#define KC      64                      // K elements per chunk (128 bytes fp16)
#define STAGES  3
#define A_BYTES (128 * KC * 2)          // 16384: A tile 128 rows
#define B_BYTES (128 * KC * 2)          // 16384: B tile 128 rows (2 halves of 64)
#define STAGE_B (A_BYTES + B_BYTES)     // 32768
#define SMEM_DYN (STAGES * STAGE_B + 1024)   // ~99 KB -> 2 CTAs/SM

// ---------------- scratch (static device globals) ----------------
__device__ __align__(16) __half g_ax   [(size_t)NSLOT * HDIM];            // sorted A, fp16
__device__ __align__(16) __half g_w1t  [(size_t)NEXP * 2 * IDIM * HDIM];  // [E][2816][2048]
__device__ __align__(16) __half g_w2t  [(size_t)NEXP * HDIM * IDIM];      // [E][2048][1408]
__device__ __align__(16) __half g_inter[(size_t)NSLOT * IDIM];            // fp16 SwiGLU out
__device__ __align__(16) __half g_outs [(size_t)NSLOT * HDIM];            // fp16 expert out
__device__ int g_pos2slot[NSLOT];
__device__ int g_slot2pos[NSLOT];
__device__ int g_tile_e[MAXT], g_tile_r0[MAXT], g_tile_rows[MAXT];
__device__ int g_ntiles;

// ---------------- PTX helpers ----------------
__device__ __forceinline__ uint32_t smem_u32(const void* p) {
    uint32_t a;
    asm("{ .reg .u64 t; cvta.to.shared.u64 t, %1; cvt.u32.u64 %0, t; }"
        : "=r"(a) : "l"(p));
    return a;
}
__device__ __forceinline__ void mbar_init(uint32_t a, uint32_t cnt) {
    asm volatile("mbarrier.init.shared.b64 [%0], %1;" :: "r"(a), "r"(cnt) : "memory");
}
__device__ __forceinline__ void mbar_expect(uint32_t a, uint32_t bytes) {
    asm volatile("mbarrier.arrive.expect_tx.shared.b64 _, [%0], %1;"
                 :: "r"(a), "r"(bytes) : "memory");
}
__device__ __forceinline__ void mbar_arrive(uint32_t a) {
    asm volatile("mbarrier.arrive.shared.b64 _, [%0];" :: "r"(a) : "memory");
}
__device__ __forceinline__ void mbar_wait(uint32_t a, uint32_t parity) {
    asm volatile(
        "{\n\t.reg .pred P;\n\t"
        "WL%=:\n\t"
        "mbarrier.try_wait.parity.acquire.cta.shared::cta.b64 P, [%0], %1, 0x989680;\n\t"
        "@P bra WD%=;\n\t"
        "bra WL%=;\n\t"
        "WD%=:\n\t}"
        :: "r"(a), "r"(parity) : "memory");
}
__device__ __forceinline__ void tma3d(uint32_t dst, const CUtensorMap* tm,
                                      int x, int y, int z, uint32_t mbar) {
    asm volatile(
        "cp.async.bulk.tensor.3d.shared::cta.global.tile.mbarrier::complete_tx::bytes "
        "[%0], [%1, {%2, %3, %4}], [%5];"
        :: "r"(dst), "l"(tm), "r"(x), "r"(y), "r"(z), "r"(mbar) : "memory");
}
__device__ __forceinline__ void ldsm4(uint32_t r[4], uint32_t addr) {
    asm volatile("ldmatrix.sync.aligned.m8n8.x4.shared.b16 {%0,%1,%2,%3}, [%4];"
                 : "=r"(r[0]), "=r"(r[1]), "=r"(r[2]), "=r"(r[3]) : "r"(addr));
}
__device__ __forceinline__ void mma16816(float c[4], const uint32_t a[4],
                                         uint32_t b0, uint32_t b1) {
    asm volatile(
        "mma.sync.aligned.m16n8k16.row.col.f32.f16.f16.f32 "
        "{%0,%1,%2,%3}, {%4,%5,%6,%7}, {%8,%9}, {%0,%1,%2,%3};"
        : "+f"(c[0]), "+f"(c[1]), "+f"(c[2]), "+f"(c[3])
        : "r"(a[0]), "r"(a[1]), "r"(a[2]), "r"(a[3]), "r"(b0), "r"(b1));
}
__device__ __forceinline__ uint32_t sw128(uint32_t off) {
    return off ^ ((off >> 3) & 0x70);
}

// ---------------- routing ----------------
__global__ void route_kernel(const int* __restrict__ topk_idx) {
    __shared__ int cnt[NEXP];
    __shared__ int cur[NEXP];
    int tid = threadIdx.x;
    if (tid < NEXP) cnt[tid] = 0;
    __syncthreads();
    for (int s = tid; s < NSLOT; s += blockDim.x)
        atomicAdd(&cnt[topk_idx[s]], 1);
    __syncthreads();
    if (tid == 0) {
        int off = 0, t = 0;
        for (int e = 0; e < NEXP; e++) {
            cur[e] = off;
            int c = cnt[e];
            for (int r = 0; r < c; r += BM) {
                g_tile_e[t] = e;
                g_tile_r0[t] = off + r;
                g_tile_rows[t] = (c - r < BM) ? (c - r) : BM;
                t++;
            }
            off += c;
        }
        g_ntiles = t;
    }
    __syncthreads();
    for (int s = tid; s < NSLOT; s += blockDim.x) {
        int p = atomicAdd(&cur[topk_idx[s]], 1);
        g_pos2slot[p] = s;
        g_slot2pos[s] = p;
    }
}

// ---------------- gather + fp16 convert of A ----------------
__global__ void gather_x_kernel(const float* __restrict__ x) {
    int pos = blockIdx.x;
    int token = g_pos2slot[pos] / TOPK;
    const float4* src = (const float4*)(x + (size_t)token * HDIM);
    uint2* dst = (uint2*)(g_ax + (size_t)pos * HDIM);
    for (int c = threadIdx.x; c < HDIM / 4; c += blockDim.x) {
        float4 v = src[c];
        __half2 a = __floats2half2_rn(v.x, v.y);
        __half2 b = __floats2half2_rn(v.z, v.w);
        uint2 u;
        u.x = *(uint32_t*)&a;
        u.y = *(uint32_t*)&b;
        dst[c] = u;
    }
}

// ---------------- weight transpose + fp16 convert (64x64 tiles) -------------
// src [K][N] fp32 -> dst [N][K] fp16.  Loads float4-coalesced, stores 128B/warp-row.
template <int SRC_ROW, int DST_ROW>
__device__ __forceinline__ void transpose64(const float* __restrict__ src,
                                            __half* __restrict__ dst,
                                            int k0, int n0) {
    __shared__ float t[64][65];   // t[n][k]
    int tid = threadIdx.x;        // 256
#pragma unroll
    for (int p = 0; p < 4; p++) {
        int kr = p * 16 + (tid >> 4);
        int nc = (tid & 15) * 4;
        float4 v = *(const float4*)(src + (size_t)(k0 + kr) * SRC_ROW + n0 + nc);
        t[nc + 0][kr] = v.x;
        t[nc + 1][kr] = v.y;
        t[nc + 2][kr] = v.z;
        t[nc + 3][kr] = v.w;
    }
    __syncthreads();
    int nr = tid >> 5, tx = tid & 31;
#pragma unroll
    for (int p = 0; p < 8; p++) {
        int n = p * 8 + nr;
        __half2 h = __floats2half2_rn(t[n][2 * tx], t[n][2 * tx + 1]);
        *(__half2*)(dst + (size_t)(n0 + n) * DST_ROW + k0 + 2 * tx) = h;
    }
}
// gate_up [E][H][2I] fp32 -> g_w1t [E][2I][H] fp16.
// Grid: (HDIM/64, 2*IDIM/64, E)  ->  k0 from blockIdx.x (H), n0 from blockIdx.y (2I).
__global__ __launch_bounds__(256) void transpose_w1_kernel(const float* __restrict__ w) {
    int e = blockIdx.z;
    transpose64<2 * IDIM, HDIM>(w + (size_t)e * HDIM * (2 * IDIM),
                                g_w1t + (size_t)e * (2 * IDIM) * HDIM,
                                blockIdx.x * 64, blockIdx.y * 64);
}
// down [E][I][H] fp32 -> g_w2t [E][H][I] fp16.
// Grid: (IDIM/64, HDIM/64, E)  ->  k0 from blockIdx.x (I), n0 from blockIdx.y (H).
__global__ __launch_bounds__(256) void transpose_w2_kernel(const float* __restrict__ w) {
    int e = blockIdx.z;
    transpose64<HDIM, IDIM>(w + (size_t)e * IDIM * HDIM,
                            g_w2t + (size_t)e * HDIM * IDIM,
                            blockIdx.x * 64, blockIdx.y * 64);
}

// ---------------- HMMA mainloop: M=128 x N=(64+64), 3-stage, 2 CTAs/SM ------
__device__ __forceinline__ void hmma_mainloop(
    uint32_t sb, const CUtensorMap* tA, const CUtensorMap* tB,
    int row0, int y0, int y1, int ez, int nchunks, float acc[2][8][4])
{
    __shared__ __align__(8) unsigned long long mbar[2 * STAGES];
    int tid = threadIdx.x;
    uint32_t fb = smem_u32(&mbar[0]);
    uint32_t eb = smem_u32(&mbar[STAGES]);
    if (tid == 0) {
        for (int s = 0; s < STAGES; s++) {
            mbar_init(fb + 8u * s, 1);
            mbar_init(eb + 8u * s, 256);
        }
    }
    __syncthreads();
    if (tid == 0) {
        int npre = (STAGES < nchunks) ? STAGES : nchunks;
        for (int c = 0; c < npre; c++) {
            uint32_t st = sb + c * STAGE_B;
            mbar_expect(fb + 8u * c, STAGE_B);
            tma3d(st,                          tA, c * KC, row0, 0,  fb + 8u * c);
            tma3d(st + A_BYTES,                tB, c * KC, y0,   ez, fb + 8u * c);
            tma3d(st + A_BYTES + B_BYTES / 2,  tB, c * KC, y1,   ez, fb + 8u * c);
        }
    }
    int lane = tid & 31, warp = tid >> 5;
    int wm = warp >> 1, wn = warp & 1;               // 4m x 2n warp grid
    int aRow = wm * 32 + (lane & 15);                // + mt*16
    int aKb  = (lane >> 4) << 4;                     // + ks*32
    int bRow = wn * 32 + (lane & 7) + ((lane >> 4) << 3);  // + pp*16 (+64 half1)
    int bKb  = ((lane >> 3) & 1) << 4;               // + ks*32

    int s = 0, parity = 0;
    for (int c = 0; c < nchunks; c++) {
        uint32_t st = sb + s * STAGE_B;
        mbar_wait(fb + 8u * s, parity);
        uint32_t aB = st, bB = st + A_BYTES;
#pragma unroll
        for (int ks = 0; ks < KC / 16; ks++) {
            uint32_t a[2][4];
#pragma unroll
            for (int mt = 0; mt < 2; mt++) {
                uint32_t off = (uint32_t)(aRow + mt * 16) * 128 + aKb + ks * 32;
                ldsm4(a[mt], aB + sw128(off));
            }
#pragma unroll
            for (int half = 0; half < 2; half++) {
#pragma unroll
                for (int pp = 0; pp < 2; pp++) {
                    uint32_t off = (uint32_t)(half * 64 + bRow + pp * 16) * 128
                                   + bKb + ks * 32;
                    uint32_t b[4];
                    ldsm4(b, bB + sw128(off));
                    int nt = half * 4 + pp * 2;
                    mma16816(acc[0][nt],     a[0], b[0], b[1]);
                    mma16816(acc[0][nt + 1], a[0], b[2], b[3]);
                    mma16816(acc[1][nt],     a[1], b[0], b[1]);
                    mma16816(acc[1][nt + 1], a[1], b[2], b[3]);
                }
            }
        }
        mbar_arrive(eb + 8u * s);
        if (tid == 0 && c + STAGES < nchunks) {
            mbar_wait(eb + 8u * s, parity);
            int cn = c + STAGES;
            mbar_expect(fb + 8u * s, STAGE_B);
            tma3d(st,                         tA, cn * KC, row0, 0,  fb + 8u * s);
            tma3d(st + A_BYTES,               tB, cn * KC, y0,   ez, fb + 8u * s);
            tma3d(st + A_BYTES + B_BYTES / 2, tB, cn * KC, y1,   ez, fb + 8u * s);
        }
        if (++s == STAGES) { s = 0; parity ^= 1; }
    }
}

// ---------------- GEMM1: A_sorted @ w1t (gate+up) + fused SwiGLU ------------
__global__ __launch_bounds__(256, 2) void gemm1_tc(
    const __grid_constant__ CUtensorMap tA,
    const __grid_constant__ CUtensorMap tB)
{
    int t = blockIdx.y;
    if (t >= g_ntiles) return;
    int e = g_tile_e[t], row0 = g_tile_r0[t], rows = g_tile_rows[t];
    int c0 = blockIdx.x * 64;
    extern __shared__ __align__(1024) char dsm[];
    uint32_t sb = (smem_u32(dsm) + 1023u) & ~1023u;

    float acc[2][8][4];
#pragma unroll
    for (int i = 0; i < 2; i++)
#pragma unroll
        for (int j = 0; j < 8; j++)
#pragma unroll
            for (int q = 0; q < 4; q++) acc[i][j][q] = 0.f;

    hmma_mainloop(sb, &tA, &tB, row0, c0, IDIM + c0, e, HDIM / KC, acc);

    int lane = threadIdx.x & 31, warp = threadIdx.x >> 5;
    int wm = warp >> 1, wn = warp & 1;
#pragma unroll
    for (int mt = 0; mt < 2; mt++) {
#pragma unroll
        for (int nt = 0; nt < 4; nt++) {
            int col = c0 + wn * 32 + nt * 8 + 2 * (lane & 3);
            int r_lo = wm * 32 + mt * 16 + (lane >> 2);
            float g0 = acc[mt][nt][0], g1 = acc[mt][nt][1];
            float u0 = acc[mt][nt + 4][0], u1 = acc[mt][nt + 4][1];
            if (r_lo < rows) {
                float o0 = u0 * (g0 / (1.f + __expf(-g0)));
                float o1 = u1 * (g1 / (1.f + __expf(-g1)));
                __half2 p = __floats2half2_rn(o0, o1);
                *(__half2*)(g_inter + (size_t)(row0 + r_lo) * IDIM + col) = p;
            }
            int r_hi = r_lo + 8;
            g0 = acc[mt][nt][2]; g1 = acc[mt][nt][3];
            u0 = acc[mt][nt + 4][2]; u1 = acc[mt][nt + 4][3];
            if (r_hi < rows) {
                float o0 = u0 * (g0 / (1.f + __expf(-g0)));
                float o1 = u1 * (g1 / (1.f + __expf(-g1)));
                __half2 p = __floats2half2_rn(o0, o1);
                *(__half2*)(g_inter + (size_t)(row0 + r_hi) * IDIM + col) = p;
            }
        }
    }
}

// ---------------- GEMM2: g_inter @ w2t -> g_outs (fp16) ---------------------
__global__ __launch_bounds__(256, 2) void gemm2_tc(
    const __grid_constant__ CUtensorMap tA,
    const __grid_constant__ CUtensorMap tB)
{
    int t = blockIdx.y;
    if (t >= g_ntiles) return;
    int e = g_tile_e[t], row0 = g_tile_r0[t], rows = g_tile_rows[t];
    int n0 = blockIdx.x * 128;
    extern __shared__ __align__(1024) char dsm[];
    uint32_t sb = (smem_u32(dsm) + 1023u) & ~1023u;

    float acc[2][8][4];
#pragma unroll
    for (int i = 0; i < 2; i++)
#pragma unroll
        for (int j = 0; j < 8; j++)
#pragma unroll
            for (int q = 0; q < 4; q++) acc[i][j][q] = 0.f;

    hmma_mainloop(sb, &tA, &tB, row0, n0, n0 + 64, e, IDIM / KC, acc);

    int lane = threadIdx.x & 31, warp = threadIdx.x >> 5;
    int wm = warp >> 1, wn = warp & 1;
#pragma unroll
    for (int mt = 0; mt < 2; mt++) {
#pragma unroll
        for (int nt = 0; nt < 8; nt++) {
            int colh = (nt < 4) ? (wn * 32 + nt * 8) : (64 + wn * 32 + (nt - 4) * 8);
            int col = n0 + colh + 2 * (lane & 3);
            int r_lo = wm * 32 + mt * 16 + (lane >> 2);
            if (r_lo < rows) {
                __half2 v = __floats2half2_rn(acc[mt][nt][0], acc[mt][nt][1]);
                *(__half2*)(g_outs + (size_t)(row0 + r_lo) * HDIM + col) = v;
            }
            int r_hi = r_lo + 8;
            if (r_hi < rows) {
                __half2 v = __floats2half2_rn(acc[mt][nt][2], acc[mt][nt][3]);
                *(__half2*)(g_outs + (size_t)(row0 + r_hi) * HDIM + col) = v;
            }
        }
    }
}

// ---------------- combine: weighted unroute (fp16 g_outs) -------------------
__global__ void combine_kernel(const float* __restrict__ tw,
                               float* __restrict__ out) {
    const int HQ = HDIM / 4;
    int idx = blockIdx.x * blockDim.x + threadIdx.x;
    if (idx >= N_TOK * HQ) return;
    int n = idx / HQ;
    int hq = idx - n * HQ;
    int p0 = g_slot2pos[n * TOPK + 0];
    int p1 = g_slot2pos[n * TOPK + 1];
    float w0 = tw[n * TOPK + 0];
    float w1 = tw[n * TOPK + 1];
    uint2 a = ((const uint2*)(g_outs + (size_t)p0 * HDIM))[hq];
    uint2 b = ((const uint2*)(g_outs + (size_t)p1 * HDIM))[hq];
    float2 a0 = __half22float2(*(__half2*)&a.x);
    float2 a1 = __half22float2(*(__half2*)&a.y);
    float2 b0 = __half22float2(*(__half2*)&b.x);
    float2 b1 = __half22float2(*(__half2*)&b.y);
    float4 r;
    r.x = w0 * a0.x + w1 * b0.x;
    r.y = w0 * a0.y + w1 * b0.y;
    r.z = w0 * a1.x + w1 * b1.x;
    r.w = w0 * a1.y + w1 * b1.y;
    ((float4*)out)[idx] = r;
}

// ---------------- host ----------------
typedef CUresult (*encfn_t)(CUtensorMap*, CUtensorMapDataType, cuuint32_t, void*,
                            const cuuint64_t*, const cuuint64_t*, const cuuint32_t*,
                            const cuuint32_t*, CUtensorMapInterleave, CUtensorMapSwizzle,
                            CUtensorMapL2promotion, CUtensorMapFloatOOBfill);

static void enc_f16(encfn_t fn, CUtensorMap* m, void* p,
                    unsigned long long d0, unsigned long long d1, unsigned long long d2,
                    unsigned long long s1, unsigned long long s2, unsigned box1) {
    cuuint64_t dims[3] = {d0, d1, d2};
    cuuint64_t str[2]  = {s1, s2};
    cuuint32_t box[3]  = {KC, box1, 1};
    cuuint32_t es[3]   = {1, 1, 1};
    fn(m, CU_TENSOR_MAP_DATA_TYPE_FLOAT16, 3, p, dims, str, box, es,
       CU_TENSOR_MAP_INTERLEAVE_NONE, CU_TENSOR_MAP_SWIZZLE_128B,
       CU_TENSOR_MAP_L2_PROMOTION_L2_128B, CU_TENSOR_MAP_FLOAT_OOB_FILL_NONE);
}

extern "C" void kernel_launch(void* const* d_in, const int* in_sizes, int n_in,
                              void* d_out, int out_size) {
    const float* x  = (const float*)d_in[0];
    const int*   ti = (const int*)  d_in[1];
    const float* tw = (const float*)d_in[2];
    const float* gu = (const float*)d_in[3];
    const float* dn = (const float*)d_in[4];
    float* out = (float*)d_out;

    void* fp = nullptr;
    cudaDriverEntryPointQueryResult qr;
    cudaGetDriverEntryPointByVersion("cuTensorMapEncodeTiled", &fp, 12000,
                                     cudaEnableDefault, &qr);
    encfn_t fn = (encfn_t)fp;

    void *pax, *pw1, *pw2, *pint;
    cudaGetSymbolAddress(&pax,  g_ax);
    cudaGetSymbolAddress(&pw1,  g_w1t);
    cudaGetSymbolAddress(&pw2,  g_w2t);
    cudaGetSymbolAddress(&pint, g_inter);

    CUtensorMap tA1, tB1, tA2, tB2;
    enc_f16(fn, &tA1, pax, HDIM, NSLOT, 1,
            (unsigned long long)HDIM * 2, (unsigned long long)HDIM * 2 * NSLOT, 128);
    enc_f16(fn, &tB1, pw1, HDIM, 2 * IDIM, NEXP,
            (unsigned long long)HDIM * 2, (unsigned long long)HDIM * 2 * 2 * IDIM, 64);
    enc_f16(fn, &tA2, pint, IDIM, NSLOT, 1,
            (unsigned long long)IDIM * 2, (unsigned long long)IDIM * 2 * NSLOT, 128);
    enc_f16(fn, &tB2, pw2, IDIM, HDIM, NEXP,
            (unsigned long long)IDIM * 2, (unsigned long long)IDIM * 2 * HDIM, 64);

    cudaFuncSetAttribute(gemm1_tc, cudaFuncAttributeMaxDynamicSharedMemorySize, SMEM_DYN);
    cudaFuncSetAttribute(gemm2_tc, cudaFuncAttributeMaxDynamicSharedMemorySize, SMEM_DYN);

    route_kernel<<<1, 256>>>(ti);
    gather_x_kernel<<<NSLOT, 256>>>(x);
    transpose_w1_kernel<<<dim3(HDIM / 64, 2 * IDIM / 64, NEXP), 256>>>(gu);
    transpose_w2_kernel<<<dim3(IDIM / 64, HDIM / 64, NEXP), 256>>>(dn);
    gemm1_tc<<<dim3(IDIM / 64, MAXT), 256, SMEM_DYN>>>(tA1, tB1);
    gemm2_tc<<<dim3(HDIM / 128, MAXT), 256, SMEM_DYN>>>(tA2, tB2);
    combine_kernel<<<(N_TOK * (HDIM / 4) + 255) / 256, 256>>>(tw, out);
}

// round 15
// speedup vs baseline: 8.3298x; 1.0089x over previous
#include <cuda_runtime.h>
#include <cuda.h>
#include <cuda_fp16.h>
#include <cstdint>

// ---------------- problem constants ----------------
#define N_TOK 8192
#define TOPK  2
#define NEXP  8
#define HDIM  2048
#define IDIM  1408
#define NSLOT (N_TOK * TOPK)           // 16384
#define BM    128
#define MAXT  (NSLOT / BM + NEXP)      // 136 worst-case M tiles

// ---------------- GEMM pipeline constants ----------------
#define KC      64                      // K elements per chunk (128 bytes fp16)
#define STAGES  3
#define A_BYTES (128 * KC * 2)          // 16384: A tile 128 rows
#define B_BYTES (128 * KC * 2)          // 16384: B tile 128 rows (2 halves of 64)
#define STAGE_B (A_BYTES + B_BYTES)     // 32768
#define SMEM_DYN (STAGES * STAGE_B + 1024)   // ~99 KB -> 2 CTAs/SM

// ---------------- scratch (static device globals) ----------------
__device__ __align__(16) __half g_ax   [(size_t)NSLOT * HDIM];            // sorted A, fp16
__device__ __align__(16) __half g_w1t  [(size_t)NEXP * 2 * IDIM * HDIM];  // [E][2816][2048]
__device__ __align__(16) __half g_w2t  [(size_t)NEXP * HDIM * IDIM];      // [E][2048][1408]
__device__ __align__(16) __half g_inter[(size_t)NSLOT * IDIM];            // fp16 SwiGLU out
__device__ __align__(16) __half g_outs [(size_t)NSLOT * HDIM];            // fp16 expert out
__device__ int g_pos2slot[NSLOT];
__device__ int g_slot2pos[NSLOT];
__device__ int g_tile_e[MAXT], g_tile_r0[MAXT], g_tile_rows[MAXT];
__device__ int g_ntiles;

// ---------------- PTX helpers ----------------
__device__ __forceinline__ uint32_t smem_u32(const void* p) {
    uint32_t a;
    asm("{ .reg .u64 t; cvta.to.shared.u64 t, %1; cvt.u32.u64 %0, t; }"
        : "=r"(a) : "l"(p));
    return a;
}
__device__ __forceinline__ void mbar_init(uint32_t a, uint32_t cnt) {
    asm volatile("mbarrier.init.shared.b64 [%0], %1;" :: "r"(a), "r"(cnt) : "memory");
}
__device__ __forceinline__ void mbar_expect(uint32_t a, uint32_t bytes) {
    asm volatile("mbarrier.arrive.expect_tx.shared.b64 _, [%0], %1;"
                 :: "r"(a), "r"(bytes) : "memory");
}
__device__ __forceinline__ void mbar_arrive(uint32_t a) {
    asm volatile("mbarrier.arrive.shared.b64 _, [%0];" :: "r"(a) : "memory");
}
__device__ __forceinline__ void mbar_wait(uint32_t a, uint32_t parity) {
    asm volatile(
        "{\n\t.reg .pred P;\n\t"
        "WL%=:\n\t"
        "mbarrier.try_wait.parity.acquire.cta.shared::cta.b64 P, [%0], %1, 0x989680;\n\t"
        "@P bra WD%=;\n\t"
        "bra WL%=;\n\t"
        "WD%=:\n\t}"
        :: "r"(a), "r"(parity) : "memory");
}
__device__ __forceinline__ void tma3d(uint32_t dst, const CUtensorMap* tm,
                                      int x, int y, int z, uint32_t mbar) {
    asm volatile(
        "cp.async.bulk.tensor.3d.shared::cta.global.tile.mbarrier::complete_tx::bytes "
        "[%0], [%1, {%2, %3, %4}], [%5];"
        :: "r"(dst), "l"(tm), "r"(x), "r"(y), "r"(z), "r"(mbar) : "memory");
}
__device__ __forceinline__ void ldsm4(uint32_t r[4], uint32_t addr) {
    asm volatile("ldmatrix.sync.aligned.m8n8.x4.shared.b16 {%0,%1,%2,%3}, [%4];"
                 : "=r"(r[0]), "=r"(r[1]), "=r"(r[2]), "=r"(r[3]) : "r"(addr));
}
__device__ __forceinline__ void mma16816(float c[4], const uint32_t a[4],
                                         uint32_t b0, uint32_t b1) {
    asm volatile(
        "mma.sync.aligned.m16n8k16.row.col.f32.f16.f16.f32 "
        "{%0,%1,%2,%3}, {%4,%5,%6,%7}, {%8,%9}, {%0,%1,%2,%3};"
        : "+f"(c[0]), "+f"(c[1]), "+f"(c[2]), "+f"(c[3])
        : "r"(a[0]), "r"(a[1]), "r"(a[2]), "r"(a[3]), "r"(b0), "r"(b1));
}
__device__ __forceinline__ uint32_t sw128(uint32_t off) {
    return off ^ ((off >> 3) & 0x70);
}

// ---------------- routing ----------------
__global__ void route_kernel(const int* __restrict__ topk_idx) {
    __shared__ int cnt[NEXP];
    __shared__ int cur[NEXP];
    int tid = threadIdx.x;
    if (tid < NEXP) cnt[tid] = 0;
    __syncthreads();
    for (int s = tid; s < NSLOT; s += blockDim.x)
        atomicAdd(&cnt[topk_idx[s]], 1);
    __syncthreads();
    if (tid == 0) {
        int off = 0, t = 0;
        for (int e = 0; e < NEXP; e++) {
            cur[e] = off;
            int c = cnt[e];
            for (int r = 0; r < c; r += BM) {
                g_tile_e[t] = e;
                g_tile_r0[t] = off + r;
                g_tile_rows[t] = (c - r < BM) ? (c - r) : BM;
                t++;
            }
            off += c;
        }
        g_ntiles = t;
    }
    __syncthreads();
    for (int s = tid; s < NSLOT; s += blockDim.x) {
        int p = atomicAdd(&cur[topk_idx[s]], 1);
        g_pos2slot[p] = s;
        g_slot2pos[s] = p;
    }
}

// ---------------- gather + fp16 convert of A ----------------
__global__ void gather_x_kernel(const float* __restrict__ x) {
    int pos = blockIdx.x;
    int token = g_pos2slot[pos] / TOPK;
    const float4* src = (const float4*)(x + (size_t)token * HDIM);
    uint2* dst = (uint2*)(g_ax + (size_t)pos * HDIM);
    for (int c = threadIdx.x; c < HDIM / 4; c += blockDim.x) {
        float4 v = src[c];
        __half2 a = __floats2half2_rn(v.x, v.y);
        __half2 b = __floats2half2_rn(v.z, v.w);
        uint2 u;
        u.x = *(uint32_t*)&a;
        u.y = *(uint32_t*)&b;
        dst[c] = u;
    }
}

// ---------------- weight transpose + fp16 convert (64x64 tiles) -------------
// src [K][N] fp32 -> dst [N][K] fp16.  Loads float4-coalesced, stores 128B/warp-row.
template <int SRC_ROW, int DST_ROW>
__device__ __forceinline__ void transpose64(const float* __restrict__ src,
                                            __half* __restrict__ dst,
                                            int k0, int n0) {
    __shared__ float t[64][65];   // t[n][k]
    int tid = threadIdx.x;        // 256
#pragma unroll
    for (int p = 0; p < 4; p++) {
        int kr = p * 16 + (tid >> 4);
        int nc = (tid & 15) * 4;
        float4 v = *(const float4*)(src + (size_t)(k0 + kr) * SRC_ROW + n0 + nc);
        t[nc + 0][kr] = v.x;
        t[nc + 1][kr] = v.y;
        t[nc + 2][kr] = v.z;
        t[nc + 3][kr] = v.w;
    }
    __syncthreads();
    int nr = tid >> 5, tx = tid & 31;
#pragma unroll
    for (int p = 0; p < 8; p++) {
        int n = p * 8 + nr;
        __half2 h = __floats2half2_rn(t[n][2 * tx], t[n][2 * tx + 1]);
        *(__half2*)(dst + (size_t)(n0 + n) * DST_ROW + k0 + 2 * tx) = h;
    }
}
// gate_up [E][H][2I] fp32 -> g_w1t [E][2I][H] fp16.
// Grid: (HDIM/64, 2*IDIM/64, E)  ->  k0 from blockIdx.x (H), n0 from blockIdx.y (2I).
__global__ __launch_bounds__(256) void transpose_w1_kernel(const float* __restrict__ w) {
    int e = blockIdx.z;
    transpose64<2 * IDIM, HDIM>(w + (size_t)e * HDIM * (2 * IDIM),
                                g_w1t + (size_t)e * (2 * IDIM) * HDIM,
                                blockIdx.x * 64, blockIdx.y * 64);
}
// down [E][I][H] fp32 -> g_w2t [E][H][I] fp16.
// Grid: (IDIM/64, HDIM/64, E)  ->  k0 from blockIdx.x (I), n0 from blockIdx.y (H).
__global__ __launch_bounds__(256) void transpose_w2_kernel(const float* __restrict__ w) {
    int e = blockIdx.z;
    transpose64<HDIM, IDIM>(w + (size_t)e * IDIM * HDIM,
                            g_w2t + (size_t)e * HDIM * IDIM,
                            blockIdx.x * 64, blockIdx.y * 64);
}

// ---------------- HMMA mainloop: M=128 x N=(64+64), 3-stage, 2 CTAs/SM ------
__device__ __forceinline__ void hmma_mainloop(
    uint32_t sb, const CUtensorMap* tA, const CUtensorMap* tB,
    int row0, int y0, int y1, int ez, int nchunks, float acc[2][8][4])
{
    __shared__ __align__(8) unsigned long long mbar[2 * STAGES];
    int tid = threadIdx.x;
    uint32_t fb = smem_u32(&mbar[0]);
    uint32_t eb = smem_u32(&mbar[STAGES]);
    if (tid == 0) {
        for (int s = 0; s < STAGES; s++) {
            mbar_init(fb + 8u * s, 1);
            mbar_init(eb + 8u * s, 256);
        }
    }
    __syncthreads();
    if (tid == 0) {
        int npre = (STAGES < nchunks) ? STAGES : nchunks;
        for (int c = 0; c < npre; c++) {
            uint32_t st = sb + c * STAGE_B;
            mbar_expect(fb + 8u * c, STAGE_B);
            tma3d(st,                          tA, c * KC, row0, 0,  fb + 8u * c);
            tma3d(st + A_BYTES,                tB, c * KC, y0,   ez, fb + 8u * c);
            tma3d(st + A_BYTES + B_BYTES / 2,  tB, c * KC, y1,   ez, fb + 8u * c);
        }
    }
    int lane = tid & 31, warp = tid >> 5;
    int wm = warp >> 1, wn = warp & 1;               // 4m x 2n warp grid
    int aRow = wm * 32 + (lane & 15);                // + mt*16
    int aKb  = (lane >> 4) << 4;                     // + ks*32
    int bRow = wn * 32 + (lane & 7) + ((lane >> 4) << 3);  // + pp*16 (+64 half1)
    int bKb  = ((lane >> 3) & 1) << 4;               // + ks*32

    int s = 0, parity = 0;
    for (int c = 0; c < nchunks; c++) {
        uint32_t st = sb + s * STAGE_B;
        mbar_wait(fb + 8u * s, parity);
        uint32_t aB = st, bB = st + A_BYTES;
#pragma unroll
        for (int ks = 0; ks < KC / 16; ks++) {
            uint32_t a[2][4];
#pragma unroll
            for (int mt = 0; mt < 2; mt++) {
                uint32_t off = (uint32_t)(aRow + mt * 16) * 128 + aKb + ks * 32;
                ldsm4(a[mt], aB + sw128(off));
            }
#pragma unroll
            for (int half = 0; half < 2; half++) {
#pragma unroll
                for (int pp = 0; pp < 2; pp++) {
                    uint32_t off = (uint32_t)(half * 64 + bRow + pp * 16) * 128
                                   + bKb + ks * 32;
                    uint32_t b[4];
                    ldsm4(b, bB + sw128(off));
                    int nt = half * 4 + pp * 2;
                    mma16816(acc[0][nt],     a[0], b[0], b[1]);
                    mma16816(acc[0][nt + 1], a[0], b[2], b[3]);
                    mma16816(acc[1][nt],     a[1], b[0], b[1]);
                    mma16816(acc[1][nt + 1], a[1], b[2], b[3]);
                }
            }
        }
        mbar_arrive(eb + 8u * s);
        if (tid == 0 && c + STAGES < nchunks) {
            mbar_wait(eb + 8u * s, parity);
            int cn = c + STAGES;
            mbar_expect(fb + 8u * s, STAGE_B);
            tma3d(st,                         tA, cn * KC, row0, 0,  fb + 8u * s);
            tma3d(st + A_BYTES,               tB, cn * KC, y0,   ez, fb + 8u * s);
            tma3d(st + A_BYTES + B_BYTES / 2, tB, cn * KC, y1,   ez, fb + 8u * s);
        }
        if (++s == STAGES) { s = 0; parity ^= 1; }
    }
}

// ---------------- GEMM1: A_sorted @ w1t (gate+up) + fused SwiGLU ------------
__global__ __launch_bounds__(256, 2) void gemm1_tc(
    const __grid_constant__ CUtensorMap tA,
    const __grid_constant__ CUtensorMap tB)
{
    int t = blockIdx.y;
    if (t >= g_ntiles) return;
    int e = g_tile_e[t], row0 = g_tile_r0[t], rows = g_tile_rows[t];
    int c0 = blockIdx.x * 64;
    extern __shared__ __align__(1024) char dsm[];
    uint32_t sb = (smem_u32(dsm) + 1023u) & ~1023u;

    float acc[2][8][4];
#pragma unroll
    for (int i = 0; i < 2; i++)
#pragma unroll
        for (int j = 0; j < 8; j++)
#pragma unroll
            for (int q = 0; q < 4; q++) acc[i][j][q] = 0.f;

    hmma_mainloop(sb, &tA, &tB, row0, c0, IDIM + c0, e, HDIM / KC, acc);

    int lane = threadIdx.x & 31, warp = threadIdx.x >> 5;
    int wm = warp >> 1, wn = warp & 1;
#pragma unroll
    for (int mt = 0; mt < 2; mt++) {
#pragma unroll
        for (int nt = 0; nt < 4; nt++) {
            int col = c0 + wn * 32 + nt * 8 + 2 * (lane & 3);
            int r_lo = wm * 32 + mt * 16 + (lane >> 2);
            float g0 = acc[mt][nt][0], g1 = acc[mt][nt][1];
            float u0 = acc[mt][nt + 4][0], u1 = acc[mt][nt + 4][1];
            if (r_lo < rows) {
                float o0 = u0 * (g0 / (1.f + __expf(-g0)));
                float o1 = u1 * (g1 / (1.f + __expf(-g1)));
                __half2 p = __floats2half2_rn(o0, o1);
                *(__half2*)(g_inter + (size_t)(row0 + r_lo) * IDIM + col) = p;
            }
            int r_hi = r_lo + 8;
            g0 = acc[mt][nt][2]; g1 = acc[mt][nt][3];
            u0 = acc[mt][nt + 4][2]; u1 = acc[mt][nt + 4][3];
            if (r_hi < rows) {
                float o0 = u0 * (g0 / (1.f + __expf(-g0)));
                float o1 = u1 * (g1 / (1.f + __expf(-g1)));
                __half2 p = __floats2half2_rn(o0, o1);
                *(__half2*)(g_inter + (size_t)(row0 + r_hi) * IDIM + col) = p;
            }
        }
    }
}

// ---------------- GEMM2: g_inter @ w2t -> g_outs (fp16) ---------------------
__global__ __launch_bounds__(256, 2) void gemm2_tc(
    const __grid_constant__ CUtensorMap tA,
    const __grid_constant__ CUtensorMap tB)
{
    int t = blockIdx.y;
    if (t >= g_ntiles) return;
    int e = g_tile_e[t], row0 = g_tile_r0[t], rows = g_tile_rows[t];
    int n0 = blockIdx.x * 128;
    extern __shared__ __align__(1024) char dsm[];
    uint32_t sb = (smem_u32(dsm) + 1023u) & ~1023u;

    float acc[2][8][4];
#pragma unroll
    for (int i = 0; i < 2; i++)
#pragma unroll
        for (int j = 0; j < 8; j++)
#pragma unroll
            for (int q = 0; q < 4; q++) acc[i][j][q] = 0.f;

    hmma_mainloop(sb, &tA, &tB, row0, n0, n0 + 64, e, IDIM / KC, acc);

    int lane = threadIdx.x & 31, warp = threadIdx.x >> 5;
    int wm = warp >> 1, wn = warp & 1;
#pragma unroll
    for (int mt = 0; mt < 2; mt++) {
#pragma unroll
        for (int nt = 0; nt < 8; nt++) {
            int colh = (nt < 4) ? (wn * 32 + nt * 8) : (64 + wn * 32 + (nt - 4) * 8);
            int col = n0 + colh + 2 * (lane & 3);
            int r_lo = wm * 32 + mt * 16 + (lane >> 2);
            if (r_lo < rows) {
                __half2 v = __floats2half2_rn(acc[mt][nt][0], acc[mt][nt][1]);
                *(__half2*)(g_outs + (size_t)(row0 + r_lo) * HDIM + col) = v;
            }
            int r_hi = r_lo + 8;
            if (r_hi < rows) {
                __half2 v = __floats2half2_rn(acc[mt][nt][2], acc[mt][nt][3]);
                *(__half2*)(g_outs + (size_t)(row0 + r_hi) * HDIM + col) = v;
            }
        }
    }
}

// ---------------- combine: weighted unroute (fp16 g_outs) -------------------
__global__ void combine_kernel(const float* __restrict__ tw,
                               float* __restrict__ out) {
    const int HQ = HDIM / 4;
    int idx = blockIdx.x * blockDim.x + threadIdx.x;
    if (idx >= N_TOK * HQ) return;
    int n = idx / HQ;
    int hq = idx - n * HQ;
    int p0 = g_slot2pos[n * TOPK + 0];
    int p1 = g_slot2pos[n * TOPK + 1];
    float w0 = tw[n * TOPK + 0];
    float w1 = tw[n * TOPK + 1];
    uint2 a = ((const uint2*)(g_outs + (size_t)p0 * HDIM))[hq];
    uint2 b = ((const uint2*)(g_outs + (size_t)p1 * HDIM))[hq];
    float2 a0 = __half22float2(*(__half2*)&a.x);
    float2 a1 = __half22float2(*(__half2*)&a.y);
    float2 b0 = __half22float2(*(__half2*)&b.x);
    float2 b1 = __half22float2(*(__half2*)&b.y);
    float4 r;
    r.x = w0 * a0.x + w1 * b0.x;
    r.y = w0 * a0.y + w1 * b0.y;
    r.z = w0 * a1.x + w1 * b1.x;
    r.w = w0 * a1.y + w1 * b1.y;
    ((float4*)out)[idx] = r;
}

// ---------------- host ----------------
typedef CUresult (*encfn_t)(CUtensorMap*, CUtensorMapDataType, cuuint32_t, void*,
                            const cuuint64_t*, const cuuint64_t*, const cuuint32_t*,
                            const cuuint32_t*, CUtensorMapInterleave, CUtensorMapSwizzle,
                            CUtensorMapL2promotion, CUtensorMapFloatOOBfill);

static void enc_f16(encfn_t fn, CUtensorMap* m, void* p,
                    unsigned long long d0, unsigned long long d1, unsigned long long d2,
                    unsigned long long s1, unsigned long long s2, unsigned box1) {
    cuuint64_t dims[3] = {d0, d1, d2};
    cuuint64_t str[2]  = {s1, s2};
    cuuint32_t box[3]  = {KC, box1, 1};
    cuuint32_t es[3]   = {1, 1, 1};
    fn(m, CU_TENSOR_MAP_DATA_TYPE_FLOAT16, 3, p, dims, str, box, es,
       CU_TENSOR_MAP_INTERLEAVE_NONE, CU_TENSOR_MAP_SWIZZLE_128B,
       CU_TENSOR_MAP_L2_PROMOTION_L2_128B, CU_TENSOR_MAP_FLOAT_OOB_FILL_NONE);
}

extern "C" void kernel_launch(void* const* d_in, const int* in_sizes, int n_in,
                              void* d_out, int out_size) {
    const float* x  = (const float*)d_in[0];
    const int*   ti = (const int*)  d_in[1];
    const float* tw = (const float*)d_in[2];
    const float* gu = (const float*)d_in[3];
    const float* dn = (const float*)d_in[4];
    float* out = (float*)d_out;

    // one-time host resources (created on the uncaptured correctness call;
    // reused identically on every call -> same captured topology each time)
    static cudaStream_t st1 = nullptr, st2 = nullptr;
    static cudaEvent_t evRoot, evW1, evW2;
    if (st1 == nullptr) {
        cudaStreamCreateWithFlags(&st1, cudaStreamNonBlocking);
        cudaStreamCreateWithFlags(&st2, cudaStreamNonBlocking);
        cudaEventCreateWithFlags(&evRoot, cudaEventDisableTiming);
        cudaEventCreateWithFlags(&evW1, cudaEventDisableTiming);
        cudaEventCreateWithFlags(&evW2, cudaEventDisableTiming);
    }

    void* fp = nullptr;
    cudaDriverEntryPointQueryResult qr;
    cudaGetDriverEntryPointByVersion("cuTensorMapEncodeTiled", &fp, 12000,
                                     cudaEnableDefault, &qr);
    encfn_t fn = (encfn_t)fp;

    void *pax, *pw1, *pw2, *pint;
    cudaGetSymbolAddress(&pax,  g_ax);
    cudaGetSymbolAddress(&pw1,  g_w1t);
    cudaGetSymbolAddress(&pw2,  g_w2t);
    cudaGetSymbolAddress(&pint, g_inter);

    CUtensorMap tA1, tB1, tA2, tB2;
    enc_f16(fn, &tA1, pax, HDIM, NSLOT, 1,
            (unsigned long long)HDIM * 2, (unsigned long long)HDIM * 2 * NSLOT, 128);
    enc_f16(fn, &tB1, pw1, HDIM, 2 * IDIM, NEXP,
            (unsigned long long)HDIM * 2, (unsigned long long)HDIM * 2 * 2 * IDIM, 64);
    enc_f16(fn, &tA2, pint, IDIM, NSLOT, 1,
            (unsigned long long)IDIM * 2, (unsigned long long)IDIM * 2 * NSLOT, 128);
    enc_f16(fn, &tB2, pw2, IDIM, HDIM, NEXP,
            (unsigned long long)IDIM * 2, (unsigned long long)IDIM * 2 * HDIM, 64);

    cudaFuncSetAttribute(gemm1_tc, cudaFuncAttributeMaxDynamicSharedMemorySize, SMEM_DYN);
    cudaFuncSetAttribute(gemm2_tc, cudaFuncAttributeMaxDynamicSharedMemorySize, SMEM_DYN);

    cudaStream_t s0 = (cudaStream_t)0;   // capture-origin (legacy default) stream

    // Fork side streams at the very top: transposes depend only on inputs.
    cudaEventRecord(evRoot, s0);
    cudaStreamWaitEvent(st1, evRoot, 0);
    cudaStreamWaitEvent(st2, evRoot, 0);
    transpose_w1_kernel<<<dim3(HDIM / 64, 2 * IDIM / 64, NEXP), 256, 0, st1>>>(gu);
    transpose_w2_kernel<<<dim3(IDIM / 64, HDIM / 64, NEXP), 256, 0, st2>>>(dn);

    // main stream: route -> gather
    route_kernel<<<1, 256, 0, s0>>>(ti);
    gather_x_kernel<<<NSLOT, 256, 0, s0>>>(x);

    // GEMM1 joins {gather(s0), w1(st1)}
    cudaEventRecord(evW1, st1);
    cudaStreamWaitEvent(s0, evW1, 0);
    gemm1_tc<<<dim3(IDIM / 64, MAXT), 256, SMEM_DYN, s0>>>(tA1, tB1);

    // GEMM2 joins {GEMM1(s0), w2(st2)}
    cudaEventRecord(evW2, st2);
    cudaStreamWaitEvent(s0, evW2, 0);
    gemm2_tc<<<dim3(HDIM / 128, MAXT), 256, SMEM_DYN, s0>>>(tA2, tB2);

    combine_kernel<<<(N_TOK * (HDIM / 4) + 255) / 256, 256, 0, s0>>>(tw, out);
}